// round 9
// baseline (speedup 1.0000x reference)
#include <cuda_runtime.h>
#include <math.h>
#include <stdint.h>

#define BB   16
#define LL   4096
#define DD   256
#define CC   50
#define NN   512
#define EE   8192
#define FF   100
#define FP   128
#define AA   256
#define FFNH 128
#define FEAT 556   /* 256 + 3*100 */

// ---------------- one big static scratch buffer (no allocations) ------------
static constexpr size_t OFF_H     = 0;
static constexpr size_t OFF_T0    = OFF_H     + (size_t)BB*LL*DD;
static constexpr size_t OFF_T1    = OFF_T0    + (size_t)BB*LL*FP;
static constexpr size_t OFF_Z     = OFF_T1    + (size_t)BB*LL*FP;   /* [b][l][AA] */
static constexpr size_t OFF_LOG   = OFF_Z     + (size_t)BB*LL*AA;   /* [b][c][l] */
static constexpr size_t OFF_WEX   = OFF_LOG   + (size_t)BB*CC*LL;   /* [b][c][l] */
static constexpr size_t OFF_V     = OFF_WEX   + (size_t)BB*CC*LL;
static constexpr size_t OFF_WA    = OFF_V     + (size_t)3*BB*CC*FF;   /* 3 x 9*DD*FP */
static constexpr size_t OFF_WB    = OFF_WA    + (size_t)3*9*DD*FP;    /* 6 x 9*FP*FP */
static constexpr size_t OFF_AWP   = OFF_WB    + (size_t)6*9*FP*FP;    /* 3 x FP*AA  */
static constexpr size_t OFF_AUP   = OFF_AWP   + (size_t)3*FP*AA;      /* 3 x AA*64  */
static constexpr size_t OFF_GWT   = OFF_AUP   + (size_t)3*AA*64;      /* 2 x DD*DD  */
static constexpr size_t OFF_XN    = OFF_GWT   + (size_t)2*DD*DD;
static constexpr size_t OFF_XW    = OFF_XN    + (size_t)BB*NN*DD;
static constexpr size_t OFF_G1    = OFF_XW    + (size_t)BB*NN*DD;
static constexpr size_t OFF_GOUT  = OFF_G1    + (size_t)BB*NN*DD;
static constexpr size_t OFF_F1T   = OFF_GOUT  + (size_t)BB*CC*DD;
static constexpr size_t OFF_DINV  = OFF_F1T   + (size_t)FEAT*FFNH;
static constexpr size_t BUF_TOTAL = OFF_DINV  + (size_t)BB*NN;

__device__ float g_buf[BUF_TOTAL];
__device__ int   g_deg[BB*NN];

// ---------------- helpers ----------------------------------------------------
__device__ __forceinline__ float to_tf32(float x) {
    float r;
    asm("cvt.rna.tf32.f32 %0, %1;" : "=f"(r) : "f"(x));
    return r;
}

__device__ __forceinline__ void mma8(float d[4], const uint32_t a[4],
                                     uint32_t b0, uint32_t b1) {
    asm volatile(
        "mma.sync.aligned.m16n8k8.row.col.f32.tf32.tf32.f32 "
        "{%0,%1,%2,%3}, {%4,%5,%6,%7}, {%8,%9}, {%0,%1,%2,%3};\n"
        : "+f"(d[0]), "+f"(d[1]), "+f"(d[2]), "+f"(d[3])
        : "r"(a[0]), "r"(a[1]), "r"(a[2]), "r"(a[3]), "r"(b0), "r"(b1));
}

// 16B async copy; pred=false -> zero-fill
__device__ __forceinline__ void cp16(float* dst_smem, const float* src, bool pred) {
    uint32_t d = (uint32_t)__cvta_generic_to_shared(dst_smem);
    int sz = pred ? 16 : 0;
    asm volatile("cp.async.cg.shared.global [%0], [%1], 16, %2;\n"
                 :: "r"(d), "l"(src), "r"(sz));
}
__device__ __forceinline__ void cp_commit() {
    asm volatile("cp.async.commit_group;\n");
}
__device__ __forceinline__ void cp_wait0() {
    asm volatile("cp.async.wait_group 0;\n");
}

// ---------------- embedding gather  h[b][l][d] (tf32-rounded) ----------------
__global__ void k_embed(const int* __restrict__ x, const float* __restrict__ emb,
                        float* __restrict__ h) {
    size_t idx = (size_t)blockIdx.x * 256 + threadIdx.x;
    if (idx >= (size_t)BB*LL*DD) return;
    int d = (int)(idx & (DD - 1));
    size_t row = idx >> 8;
    h[idx] = to_tf32(emb[(size_t)x[row] * DD + d]);
}

// ---------------- merged prep kernel (18 segments) ---------------------------
struct PrepPtrs {
    const float *cw0, *cw1, *cw2;     // convw3/5/9 [F][DD][K]
    const float *rw0, *rw1, *rw2;     // resw3/5/9  [2][F][FF][K]
    const float *aw, *au, *gc1, *gc2, *f1;
    float *wA0, *wA1, *wA2;
    float *wB0, *wB1, *wB2, *wB3, *wB4, *wB5;
    float *awp, *aup, *gwt, *f1T;
};

__global__ void k_prep_all(PrepPtrs P) {
    int seg = blockIdx.y;
    int idx0 = blockIdx.x * 256 + threadIdx.x;
    int stride = gridDim.x * 256;
    if (seg < 3) {                       // wA: [K][DD][FP], CIN=DD
        int K = (seg == 0) ? 3 : (seg == 1) ? 5 : 9;
        const float* src = (seg == 0) ? P.cw0 : (seg == 1) ? P.cw1 : P.cw2;
        float* dst = (seg == 0) ? P.wA0 : (seg == 1) ? P.wA1 : P.wA2;
        int tot = K * DD * FP;
        for (int idx = idx0; idx < tot; idx += stride) {
            int f = idx & 127;
            int rem = idx >> 7;
            int d = rem % DD;
            int k = rem / DD;
            dst[idx] = (f < FF) ? to_tf32(src[(f * DD + d) * K + k]) : 0.f;
        }
    } else if (seg < 9) {                // wB: [K][FP][FP], CIN=FF
        int inst = seg - 3, br = inst >> 1, which = inst & 1;
        int K = (br == 0) ? 3 : (br == 1) ? 5 : 9;
        const float* base = (br == 0) ? P.rw0 : (br == 1) ? P.rw1 : P.rw2;
        const float* src = base + (size_t)which * FF * FF * K;
        float* dst = (inst == 0) ? P.wB0 : (inst == 1) ? P.wB1 : (inst == 2) ? P.wB2 :
                     (inst == 3) ? P.wB3 : (inst == 4) ? P.wB4 : P.wB5;
        int tot = K * FP * FP;
        for (int idx = idx0; idx < tot; idx += stride) {
            int f = idx & 127;
            int rem = idx >> 7;
            int d = rem % FP;
            int k = rem / FP;
            dst[idx] = (f < FF && d < FF) ? to_tf32(src[(f * FF + d) * K + k]) : 0.f;
        }
    } else if (seg < 12) {               // awp: Bt[k(FP)][a(AA)]
        int br = seg - 9;
        const float* src = P.aw + (size_t)br * AA * FF;
        float* dst = P.awp + (size_t)br * FP * AA;
        int tot = FP * AA;
        for (int idx = idx0; idx < tot; idx += stride) {
            int k = idx >> 8, n = idx & (AA - 1);
            dst[idx] = (k < FF) ? to_tf32(src[n * FF + k]) : 0.f;
        }
    } else if (seg < 15) {               // aup: Bt[k(AA)][c(64)]
        int br = seg - 12;
        const float* src = P.au + (size_t)br * CC * AA;
        float* dst = P.aup + (size_t)br * AA * 64;
        int tot = AA * 64;
        for (int idx = idx0; idx < tot; idx += stride) {
            int k = idx >> 6, n = idx & 63;
            dst[idx] = (n < CC) ? to_tf32(src[n * AA + k]) : 0.f;
        }
    } else if (seg < 17) {               // GCN weight transposes
        const float* src = (seg == 15) ? P.gc1 : P.gc2;
        float* dst = P.gwt + (size_t)(seg - 15) * DD * DD;
        int tot = DD * DD;
        for (int idx = idx0; idx < tot; idx += stride) {
            int k = idx >> 8, n = idx & (DD - 1);
            dst[idx] = to_tf32(src[n * DD + k]);
        }
    } else {                             // f1T
        int tot = FEAT * FFNH;
        for (int idx = idx0; idx < tot; idx += stride) {
            int h = idx & (FFNH - 1), k = idx >> 7;
            P.f1T[idx] = P.f1[h * FEAT + k];
        }
    }
}

// ---------------- conv1d 'same' via tf32 mma, cp.async + dbuf weights -------
template<int K, int CINP>
__global__ void __launch_bounds__(256, 2)
k_conv_mma(const float* __restrict__ in, const float* __restrict__ wT,
           const float* __restrict__ cb, const float* __restrict__ gamma,
           const float* __restrict__ beta, const float* __restrict__ resid,
           float* __restrict__ out, int mode) {
    constexpr int LT = 128;
    constexpr int PAD = K / 2;
    constexpr int ROWS = LT + K - 1;
    constexpr int ISTR = 36;
    constexpr int WSTR = 136;
    constexpr int WTILE = 32 * WSTR;
    extern __shared__ float smem[];
    float* s_in = smem;                 // ROWS*ISTR
    float* s_w  = smem + ROWS * ISTR;   // 2 * WTILE

    int b = blockIdx.y, l0 = blockIdx.x * LT, tid = threadIdx.x;
    int wid = tid >> 5, lane = tid & 31;
    int wl = wid >> 1, wf = wid & 1;
    int grp = lane >> 2, thr = lane & 3;

    float acc[2][8][4];
#pragma unroll
    for (int mi = 0; mi < 2; mi++)
#pragma unroll
        for (int ni = 0; ni < 8; ni++)
#pragma unroll
            for (int ci = 0; ci < 4; ci++) acc[mi][ni][ci] = 0.f;

    const float* inb = in + (size_t)b * LL * CINP;

    for (int d0 = 0; d0 < CINP; d0 += 32) {
        for (int t = tid; t < ROWS * 8; t += 256) {
            int row = t >> 3, seg = t & 7;
            int gl = l0 - PAD + row;
            cp16(&s_in[row * ISTR + seg * 4],
                 inb + (size_t)gl * CINP + d0 + seg * 4,
                 (gl >= 0 && gl < LL));
        }
        {
            const float* wk = wT + (size_t)d0 * FP;
            for (int t = tid; t < 32 * 32; t += 256) {
                int dd = t >> 5, seg = t & 31;
                cp16(&s_w[dd * WSTR + seg * 4], wk + dd * FP + seg * 4, true);
            }
        }
        cp_commit();
        cp_wait0();
        __syncthreads();
#pragma unroll
        for (int k = 0; k < K; k++) {
            if (k + 1 < K) {
                const float* wk = wT + ((size_t)(k + 1) * CINP + d0) * FP;
                float* dstw = s_w + ((k + 1) & 1) * WTILE;
                for (int t = tid; t < 32 * 32; t += 256) {
                    int dd = t >> 5, seg = t & 31;
                    cp16(&dstw[dd * WSTR + seg * 4], wk + dd * FP + seg * 4, true);
                }
                cp_commit();
            }
            const float* curw = s_w + (k & 1) * WTILE;
#pragma unroll
            for (int ds = 0; ds < 32; ds += 8) {
                uint32_t a[2][4];
#pragma unroll
                for (int mi = 0; mi < 2; mi++) {
                    int r0 = wl * 32 + mi * 16 + grp + k;
                    a[mi][0] = __float_as_uint(s_in[r0 * ISTR + ds + thr]);
                    a[mi][1] = __float_as_uint(s_in[(r0 + 8) * ISTR + ds + thr]);
                    a[mi][2] = __float_as_uint(s_in[r0 * ISTR + ds + thr + 4]);
                    a[mi][3] = __float_as_uint(s_in[(r0 + 8) * ISTR + ds + thr + 4]);
                }
#pragma unroll
                for (int ni = 0; ni < 8; ni++) {
                    int f = wf * 64 + ni * 8 + grp;
                    uint32_t b0 = __float_as_uint(curw[(ds + thr) * WSTR + f]);
                    uint32_t b1 = __float_as_uint(curw[(ds + thr + 4) * WSTR + f]);
                    mma8(acc[0][ni], a[0], b0, b1);
                    mma8(acc[1][ni], a[1], b0, b1);
                }
            }
            if (k + 1 < K) cp_wait0();
            __syncthreads();
        }
    }

    const float BNI = rsqrtf(1.f + 1e-5f);
#pragma unroll
    for (int mi = 0; mi < 2; mi++) {
#pragma unroll
        for (int ci = 0; ci < 4; ci++) {
            int l = l0 + wl * 32 + mi * 16 + grp + ((ci >= 2) ? 8 : 0);
            size_t base = ((size_t)b * LL + l) * FP;
#pragma unroll
            for (int ni = 0; ni < 8; ni++) {
                int f = wf * 64 + ni * 8 + 2 * thr + (ci & 1);
                float v = acc[mi][ni][ci];
                float o;
                if (f < FF) {
                    float sc = gamma[f] * BNI, bt = beta[f];
                    if (mode == 0) o = tanhf(v + cb[f]) * sc + bt;
                    else           o = tanhf(v * sc + bt + resid[base + f]);
                    o = to_tf32(o);
                } else {
                    o = 0.f;
                }
                out[base + f] = o;
            }
        }
    }
}

template<int K, int CINP>
constexpr int conv_smem_bytes() {
    return ((128 + K - 1) * 36 + 2 * 32 * 136) * 4;
}

// ---------------- generic tf32 NT GEMM: out[m][n] = A[m][k]*Bt[k][n] --------
// A: pre-tf32 fp32 [rows][CINP], Bt pre-tf32 [CINP][nstride].
// bt_bstr: per-batch element stride for Bt (0 for shared weights).
// aclamp: A rows >= aclamp read as zero.  mclamp/nclamp: store clamps.
template<int CINP, int WF, bool TANH, bool TRANSOUT>
__global__ void k_mma_nt(const float* __restrict__ A, const float* __restrict__ Bt,
                         float* __restrict__ out, int nstride,
                         size_t a_bstr, size_t bt_bstr, size_t o_bstr, int ostr,
                         int aclamp, int mclamp, int nclamp) {
    constexpr int NT = WF * 128;           // threads
    constexpr int WIDTH = WF * 64;         // n-tile
    constexpr int WSTR = WIDTH + 8;
    __shared__ float s_a[128 * 36];
    __shared__ float s_w[32 * WSTR];
    int b = blockIdx.z;
    int m0 = blockIdx.x * 128;
    int n0 = blockIdx.y * WIDTH;
    A += (size_t)b * a_bstr;
    Bt += (size_t)b * bt_bstr;
    out += (size_t)b * o_bstr;
    int tid = threadIdx.x;
    int wid = tid >> 5, lane = tid & 31;
    int wl = wid / WF, wf = wid % WF;
    int grp = lane >> 2, thr = lane & 3;

    float acc[2][8][4];
#pragma unroll
    for (int mi = 0; mi < 2; mi++)
#pragma unroll
        for (int ni = 0; ni < 8; ni++)
#pragma unroll
            for (int ci = 0; ci < 4; ci++) acc[mi][ni][ci] = 0.f;

    for (int k0 = 0; k0 < CINP; k0 += 32) {
        __syncthreads();
        for (int t = tid; t < 128 * 8; t += NT) {
            int row = t >> 3, seg = t & 7;
            cp16(&s_a[row * 36 + seg * 4],
                 A + (size_t)(m0 + row) * CINP + k0 + seg * 4,
                 (m0 + row) < aclamp);
        }
        for (int t = tid; t < 32 * (WIDTH / 4); t += NT) {
            int dd = t / (WIDTH / 4), seg = t % (WIDTH / 4);
            cp16(&s_w[dd * WSTR + seg * 4],
                 Bt + (size_t)(k0 + dd) * nstride + n0 + seg * 4, true);
        }
        cp_commit();
        cp_wait0();
        __syncthreads();
#pragma unroll
        for (int ds = 0; ds < 32; ds += 8) {
            uint32_t a[2][4];
#pragma unroll
            for (int mi = 0; mi < 2; mi++) {
                int r0 = wl * 32 + mi * 16 + grp;
                a[mi][0] = __float_as_uint(s_a[r0 * 36 + ds + thr]);
                a[mi][1] = __float_as_uint(s_a[(r0 + 8) * 36 + ds + thr]);
                a[mi][2] = __float_as_uint(s_a[r0 * 36 + ds + thr + 4]);
                a[mi][3] = __float_as_uint(s_a[(r0 + 8) * 36 + ds + thr + 4]);
            }
#pragma unroll
            for (int ni = 0; ni < 8; ni++) {
                int f = wf * 64 + ni * 8 + grp;
                uint32_t b0 = __float_as_uint(s_w[(ds + thr) * WSTR + f]);
                uint32_t b1 = __float_as_uint(s_w[(ds + thr + 4) * WSTR + f]);
                mma8(acc[0][ni], a[0], b0, b1);
                mma8(acc[1][ni], a[1], b0, b1);
            }
        }
    }

#pragma unroll
    for (int mi = 0; mi < 2; mi++) {
#pragma unroll
        for (int ci = 0; ci < 4; ci++) {
            int mrow = wl * 32 + mi * 16 + grp + ((ci >= 2) ? 8 : 0);
#pragma unroll
            for (int ni = 0; ni < 8; ni++) {
                int n = wf * 64 + ni * 8 + 2 * thr + (ci & 1);
                float v = acc[mi][ni][ci];
                if (TANH) v = to_tf32(tanhf(v));
                if (TRANSOUT) {
                    int c = n0 + n;
                    if (c < nclamp) out[(size_t)c * LL + m0 + mrow] = v;
                } else {
                    if ((m0 + mrow) < mclamp && n0 + n < nclamp)
                        out[(size_t)(m0 + mrow) * ostr + n0 + n] = v;
                }
            }
        }
    }
}

// ---------------- softmax + normalized weight write --------------------------
__global__ void k_soft(const float* __restrict__ logits, float* __restrict__ wex) {
    __shared__ float sred[256];
    int c = blockIdx.x, b = blockIdx.y, tid = threadIdx.x;
    const float* row = logits + ((size_t)b * CC + c) * LL;
    float* wrow = wex + ((size_t)b * CC + c) * LL;
    float m = -1e30f;
    for (int l = tid; l < LL; l += 256) m = fmaxf(m, row[l]);
    sred[tid] = m; __syncthreads();
    for (int s = 128; s > 0; s >>= 1) {
        if (tid < s) sred[tid] = fmaxf(sred[tid], sred[tid + s]);
        __syncthreads();
    }
    m = sred[0]; __syncthreads();
    float sum = 0.f;
    for (int l = tid; l < LL; l += 256) sum += expf(row[l] - m);
    sred[tid] = sum; __syncthreads();
    for (int s = 128; s > 0; s >>= 1) {
        if (tid < s) sred[tid] += sred[tid + s];
        __syncthreads();
    }
    float si = 1.f / sred[0];
    for (int l = tid; l < LL; l += 256)
        wrow[l] = to_tf32(expf(row[l] - m) * si);
}

// ---------------- GCN ------------------------------------------------------
__global__ void k_nodes(const int* __restrict__ nodes, const float* __restrict__ emb,
                        float* __restrict__ xn) {
    size_t idx = (size_t)blockIdx.x * 256 + threadIdx.x;
    if (idx >= (size_t)BB * NN * DD) return;
    int d = (int)(idx & (DD - 1));
    size_t row = idx >> 8;
    xn[idx] = to_tf32(emb[(size_t)nodes[row] * DD + d]);
}

__global__ void k_deginit(int* __restrict__ deg) {
    int idx = blockIdx.x * 256 + threadIdx.x;
    if (idx < BB * NN) deg[idx] = 1;   // self loop
}

__global__ void k_degadd(const int* __restrict__ edges, int* __restrict__ deg) {
    int idx = blockIdx.x * 256 + threadIdx.x;
    if (idx >= BB * EE) return;
    int b = idx / EE, e = idx % EE;
    int dst = edges[(b * 2 + 1) * EE + e];
    atomicAdd(&deg[b * NN + dst], 1);
}

__global__ void k_dinv(const int* __restrict__ deg, float* __restrict__ dinv) {
    int idx = blockIdx.x * 256 + threadIdx.x;
    if (idx < BB * NN) dinv[idx] = rsqrtf((float)deg[idx]);
}

__global__ void k_self(const float* __restrict__ xw, const float* __restrict__ dinv,
                       float* __restrict__ out, int rows) {
    size_t idx = (size_t)blockIdx.x * 256 + threadIdx.x;
    if (idx >= (size_t)BB * rows * DD) return;
    int o = (int)(idx & (DD - 1));
    size_t row = idx >> 8;
    int b = (int)(row / rows);
    int n = (int)(row % rows);
    float di = dinv[b * NN + n];
    out[idx] = di * di * xw[((size_t)b * NN + n) * DD + o];
}

__global__ void k_edge(const int* __restrict__ edges, const float* __restrict__ dinv,
                       const float* __restrict__ xw, float* __restrict__ out,
                       int dstmax) {
    int b = blockIdx.y;
    int eloc = threadIdx.x >> 5, lane = threadIdx.x & 31;
    int e = blockIdx.x * 8 + eloc;
    int src = edges[(b * 2) * EE + e];
    int dst = edges[(b * 2 + 1) * EE + e];
    if (dst >= dstmax) return;
    float norm = dinv[b * NN + src] * dinv[b * NN + dst];
    const float* xr = xw + ((size_t)b * NN + src) * DD;
    float* orow = out + ((size_t)b * dstmax + dst) * DD;
#pragma unroll
    for (int j = 0; j < 8; j++) {
        int o = lane + j * 32;
        atomicAdd(&orow[o], norm * xr[o]);
    }
}

__global__ void k_post(float* __restrict__ buf, const float* __restrict__ bias,
                       int rows, int dorelu) {
    size_t idx = (size_t)blockIdx.x * 256 + threadIdx.x;
    if (idx >= (size_t)BB * rows * DD) return;
    int o = (int)(idx & (DD - 1));
    float v = buf[idx] + bias[o];
    if (dorelu) v = fmaxf(v, 0.f);
    buf[idx] = to_tf32(v);
}

// ---------------- final MLP --------------------------------------------------
__global__ void k_final(const float* __restrict__ gout, const float* __restrict__ V,
                        const float* __restrict__ f1T, const float* __restrict__ f1b,
                        const float* __restrict__ f2w, const float* __restrict__ f2b,
                        float* __restrict__ y) {
    __shared__ float s_feat[FEAT];
    __shared__ float s_red[FFNH];
    int c = blockIdx.x, b = blockIdx.y, h = threadIdx.x;   // 128 threads
    for (int idx = h; idx < FEAT; idx += FFNH) {
        float v;
        if (idx < DD) {
            v = gout[((size_t)b * CC + c) * DD + idx];
        } else {
            int br = (idx - DD) / FF;
            int f  = (idx - DD) % FF;
            v = V[(((size_t)br * BB + b) * CC + c) * FF + f];
        }
        s_feat[idx] = v;
    }
    __syncthreads();
    float acc = f1b[h];
    for (int k = 0; k < FEAT; k++) acc += f1T[k * FFNH + h] * s_feat[k];
    float hid = fmaxf(acc, 0.f);
    s_red[h] = f2w[c * FFNH + h] * hid;
    __syncthreads();
    for (int s = 64; s > 0; s >>= 1) {
        if (h < s) s_red[h] += s_red[h + s];
        __syncthreads();
    }
    if (h == 0) y[b * CC + c] = s_red[0] + f2b[c];
}

// ---------------- branch driver (preps already done) -------------------------
template<int K>
static void run_branch(const float* cb, const float* bn_g, const float* bn_b,
                       float* buf, int br,
                       float* wA, float* wB0, float* wB1) {
    float* h    = buf + OFF_H;
    float* t0   = buf + OFF_T0;
    float* t1   = buf + OFF_T1;
    float* Z    = buf + OFF_Z;
    float* lg   = buf + OFF_LOG;
    float* wex  = buf + OFF_WEX;
    float* V    = buf + OFF_V + (size_t)br * BB * CC * FF;
    float* awp  = buf + OFF_AWP + (size_t)br * FP * AA;
    float* aup  = buf + OFF_AUP + (size_t)br * AA * 64;

    cudaFuncSetAttribute(k_conv_mma<K, DD>, cudaFuncAttributeMaxDynamicSharedMemorySize,
                         conv_smem_bytes<K, DD>());
    cudaFuncSetAttribute(k_conv_mma<K, FP>, cudaFuncAttributeMaxDynamicSharedMemorySize,
                         conv_smem_bytes<K, FP>());

    const int BIG = 1 << 30;
    dim3 cgrid(LL / 128, BB);
    k_conv_mma<K, DD><<<cgrid, 256, conv_smem_bytes<K, DD>()>>>(
        h, wA, cb, bn_g, bn_b, nullptr, t0, 0);
    k_conv_mma<K, FP><<<cgrid, 256, conv_smem_bytes<K, FP>()>>>(
        t0, wB0, nullptr, bn_g + FF, bn_b + FF, t0, t1, 1);
    k_conv_mma<K, FP><<<cgrid, 256, conv_smem_bytes<K, FP>()>>>(
        t1, wB1, nullptr, bn_g + 2 * FF, bn_b + 2 * FF, t1, t0, 1);

    // Z[b][l][a] = tanh(t0 . aw^T)
    k_mma_nt<FP, 2, true, false><<<dim3(LL / 128, AA / 128, BB), 256>>>(
        t0, awp, Z, AA, (size_t)LL * FP, 0, (size_t)LL * AA, AA, BIG, BIG, BIG);
    // logits[b][c][l] = Z . au^T (transposed store)
    k_mma_nt<AA, 1, false, true><<<dim3(LL / 128, 1, BB), 128>>>(
        Z, aup, lg, 64, (size_t)LL * AA, 0, (size_t)CC * LL, 0, BIG, BIG, CC);

    // softmax stats + normalized weights
    k_soft<<<dim3(CC, BB), 256>>>(lg, wex);

    // V[b][c][f] = wex[c][:] . t0[:][f]   (m=c pad 128, n=f pad 128, k=4096)
    // NOTE: Bt (= t0) is batched -> bt_bstr = LL*FP.
    k_mma_nt<LL, 2, false, false><<<dim3(1, 1, BB), 256>>>(
        wex, t0, V, FP, (size_t)CC * LL, (size_t)LL * FP, (size_t)CC * FF, FF,
        CC, CC, FF);
}

extern "C" void kernel_launch(void* const* d_in, const int* in_sizes, int n_in,
                              void* d_out, int out_size) {
    const int*   x        = (const int*)d_in[0];
    const int*   nodes    = (const int*)d_in[2];
    const int*   edges    = (const int*)d_in[3];
    const float* word_emb = (const float*)d_in[4];
    const float* ent_emb  = (const float*)d_in[5];
    const float* convw3   = (const float*)d_in[6];
    const float* convb3   = (const float*)d_in[7];
    const float* resw3    = (const float*)d_in[8];
    const float* convw5   = (const float*)d_in[9];
    const float* convb5   = (const float*)d_in[10];
    const float* resw5    = (const float*)d_in[11];
    const float* convw9   = (const float*)d_in[12];
    const float* convb9   = (const float*)d_in[13];
    const float* resw9    = (const float*)d_in[14];
    const float* bn_gamma = (const float*)d_in[15];
    const float* bn_beta  = (const float*)d_in[16];
    const float* attn_w   = (const float*)d_in[17];
    const float* attn_u   = (const float*)d_in[18];
    const float* gc1_w    = (const float*)d_in[19];
    const float* gc1_b    = (const float*)d_in[20];
    const float* gc2_w    = (const float*)d_in[21];
    const float* gc2_b    = (const float*)d_in[22];
    const float* fin1_w   = (const float*)d_in[23];
    const float* fin1_b   = (const float*)d_in[24];
    const float* fin2_w   = (const float*)d_in[25];
    const float* fin2_b   = (const float*)d_in[26];
    float* out = (float*)d_out;

    float* buf; int* deg;
    cudaGetSymbolAddress((void**)&buf, g_buf);
    cudaGetSymbolAddress((void**)&deg, g_deg);

    float* wA = buf + OFF_WA;
    float* wB = buf + OFF_WB;
    const size_t wA_off[3] = {0, 3 * (size_t)DD * FP, 8 * (size_t)DD * FP};
    const size_t wB_off[6] = {0, 3 * (size_t)FP * FP,
                              6 * (size_t)FP * FP, 11 * (size_t)FP * FP,
                              16 * (size_t)FP * FP, 25 * (size_t)FP * FP};

    PrepPtrs P;
    P.cw0 = convw3; P.cw1 = convw5; P.cw2 = convw9;
    P.rw0 = resw3;  P.rw1 = resw5;  P.rw2 = resw9;
    P.aw = attn_w;  P.au = attn_u;
    P.gc1 = gc1_w;  P.gc2 = gc2_w;  P.f1 = fin1_w;
    P.wA0 = wA + wA_off[0]; P.wA1 = wA + wA_off[1]; P.wA2 = wA + wA_off[2];
    P.wB0 = wB + wB_off[0]; P.wB1 = wB + wB_off[1]; P.wB2 = wB + wB_off[2];
    P.wB3 = wB + wB_off[3]; P.wB4 = wB + wB_off[4]; P.wB5 = wB + wB_off[5];
    P.awp = buf + OFF_AWP; P.aup = buf + OFF_AUP;
    P.gwt = buf + OFF_GWT; P.f1T = buf + OFF_F1T;

    // launch 1: embed; 2: all preps; 3: deg init; 4: conv<9,256> (profiled)
    k_embed<<<(int)(((size_t)BB * LL * DD + 255) / 256), 256>>>(x, word_emb, buf + OFF_H);
    k_prep_all<<<dim3(1152, 18), 256>>>(P);
    k_deginit<<<(BB * NN + 255) / 256, 256>>>(deg);

    run_branch<9>(convb9, bn_gamma + 2 * 3 * FF, bn_beta + 2 * 3 * FF, buf, 2,
                  wA + wA_off[2], wB + wB_off[4], wB + wB_off[5]);
    run_branch<3>(convb3, bn_gamma + 0 * 3 * FF, bn_beta + 0 * 3 * FF, buf, 0,
                  wA + wA_off[0], wB + wB_off[0], wB + wB_off[1]);
    run_branch<5>(convb5, bn_gamma + 1 * 3 * FF, bn_beta + 1 * 3 * FF, buf, 1,
                  wA + wA_off[1], wB + wB_off[2], wB + wB_off[3]);

    // GCN
    float* xn   = buf + OFF_XN;
    float* xw   = buf + OFF_XW;
    float* g1   = buf + OFF_G1;
    float* gout = buf + OFF_GOUT;
    float* dinv = buf + OFF_DINV;
    float* gwt1 = buf + OFF_GWT;
    float* gwt2 = buf + OFF_GWT + (size_t)DD * DD;
    const int BIG = 1 << 30;
    k_nodes<<<(int)(((size_t)BB * NN * DD + 255) / 256), 256>>>(nodes, ent_emb, xn);
    k_degadd<<<(BB * EE + 255) / 256, 256>>>(edges, deg);
    k_dinv<<<(BB * NN + 255) / 256, 256>>>(deg, dinv);

    k_mma_nt<DD, 2, false, false><<<dim3(NN / 128, DD / 128, BB), 256>>>(
        xn, gwt1, xw, DD, (size_t)NN * DD, 0, (size_t)NN * DD, DD, BIG, BIG, BIG);
    k_self<<<(int)(((size_t)BB * NN * DD + 255) / 256), 256>>>(xw, dinv, g1, NN);
    k_edge<<<dim3(EE / 8, BB), 256>>>(edges, dinv, xw, g1, NN);
    k_post<<<(int)(((size_t)BB * NN * DD + 255) / 256), 256>>>(g1, gc1_b, NN, 1);

    k_mma_nt<DD, 2, false, false><<<dim3(NN / 128, DD / 128, BB), 256>>>(
        g1, gwt2, xw, DD, (size_t)NN * DD, 0, (size_t)NN * DD, DD, BIG, BIG, BIG);
    k_self<<<(int)(((size_t)BB * CC * DD + 255) / 256), 256>>>(xw, dinv, gout, CC);
    k_edge<<<dim3(EE / 8, BB), 256>>>(edges, dinv, xw, gout, CC);
    k_post<<<(int)(((size_t)BB * CC * DD + 255) / 256), 256>>>(gout, gc2_b, CC, 0);

    // final MLP
    k_final<<<dim3(CC, BB), FFNH>>>(gout, buf + OFF_V, buf + OFF_F1T,
                                    fin1_b, fin2_w, fin2_b, out);
}

// round 12
// speedup vs baseline: 1.2114x; 1.2114x over previous
#include <cuda_runtime.h>
#include <math.h>
#include <stdint.h>

#define BB   16
#define LL   4096
#define DD   256
#define CC   50
#define NN   512
#define EE   8192
#define FF   100
#define FP   128
#define AA   256
#define FFNH 128
#define FEAT 556   /* 256 + 3*100 */

// ---------------- one big static scratch buffer (no allocations) ------------
static constexpr size_t OFF_H     = 0;
static constexpr size_t OFF_T0    = OFF_H     + (size_t)BB*LL*DD;
static constexpr size_t OFF_T1    = OFF_T0    + (size_t)BB*LL*FP;
static constexpr size_t OFF_Z     = OFF_T1    + (size_t)BB*LL*FP;   /* [b][l][AA] */
static constexpr size_t OFF_LOG   = OFF_Z     + (size_t)BB*LL*AA;   /* [b][c][l] */
static constexpr size_t OFF_RMAX  = OFF_LOG   + (size_t)BB*CC*LL;
static constexpr size_t OFF_RSINV = OFF_RMAX  + (size_t)BB*CC;
static constexpr size_t OFF_VPART = OFF_RSINV + (size_t)BB*CC;
static constexpr size_t OFF_V     = OFF_VPART + (size_t)16*BB*CC*FF;
static constexpr size_t OFF_WA    = OFF_V     + (size_t)3*BB*CC*FF;   /* 3 x 9*DD*FP */
static constexpr size_t OFF_WB    = OFF_WA    + (size_t)3*9*DD*FP;    /* 6 x 9*FP*FP */
static constexpr size_t OFF_AWP   = OFF_WB    + (size_t)6*9*FP*FP;    /* 3 x FP*AA  */
static constexpr size_t OFF_AUP   = OFF_AWP   + (size_t)3*FP*AA;      /* 3 x AA*64  */
static constexpr size_t OFF_GWT   = OFF_AUP   + (size_t)3*AA*64;      /* 2 x DD*DD  */
static constexpr size_t OFF_XN    = OFF_GWT   + (size_t)2*DD*DD;
static constexpr size_t OFF_XW    = OFF_XN    + (size_t)BB*NN*DD;
static constexpr size_t OFF_G1    = OFF_XW    + (size_t)BB*NN*DD;
static constexpr size_t OFF_GOUT  = OFF_G1    + (size_t)BB*NN*DD;
static constexpr size_t OFF_F1T   = OFF_GOUT  + (size_t)BB*CC*DD;
static constexpr size_t OFF_DINV  = OFF_F1T   + (size_t)FEAT*FFNH;
static constexpr size_t BUF_TOTAL = OFF_DINV  + (size_t)BB*NN;

__device__ float g_buf[BUF_TOTAL];
__device__ int   g_deg[BB*NN];

// ---------------- helpers ----------------------------------------------------
__device__ __forceinline__ float to_tf32(float x) {
    float r;
    asm("cvt.rna.tf32.f32 %0, %1;" : "=f"(r) : "f"(x));
    return r;
}

__device__ __forceinline__ void mma8(float d[4], const uint32_t a[4],
                                     uint32_t b0, uint32_t b1) {
    asm volatile(
        "mma.sync.aligned.m16n8k8.row.col.f32.tf32.tf32.f32 "
        "{%0,%1,%2,%3}, {%4,%5,%6,%7}, {%8,%9}, {%0,%1,%2,%3};\n"
        : "+f"(d[0]), "+f"(d[1]), "+f"(d[2]), "+f"(d[3])
        : "r"(a[0]), "r"(a[1]), "r"(a[2]), "r"(a[3]), "r"(b0), "r"(b1));
}

// 16B async copy; pred=false -> zero-fill
__device__ __forceinline__ void cp16(float* dst_smem, const float* src, bool pred) {
    uint32_t d = (uint32_t)__cvta_generic_to_shared(dst_smem);
    int sz = pred ? 16 : 0;
    asm volatile("cp.async.cg.shared.global [%0], [%1], 16, %2;\n"
                 :: "r"(d), "l"(src), "r"(sz));
}
__device__ __forceinline__ void cp_commit() {
    asm volatile("cp.async.commit_group;\n");
}
__device__ __forceinline__ void cp_wait0() {
    asm volatile("cp.async.wait_group 0;\n");
}

// ---------------- embedding gather  h[b][l][d] (tf32-rounded) ----------------
__global__ void k_embed(const int* __restrict__ x, const float* __restrict__ emb,
                        float* __restrict__ h) {
    size_t idx = (size_t)blockIdx.x * 256 + threadIdx.x;
    if (idx >= (size_t)BB*LL*DD) return;
    int d = (int)(idx & (DD - 1));
    size_t row = idx >> 8;
    h[idx] = to_tf32(emb[(size_t)x[row] * DD + d]);
}

// ---------------- merged prep kernel (18 segments) ---------------------------
struct PrepPtrs {
    const float *cw0, *cw1, *cw2;     // convw3/5/9 [F][DD][K]
    const float *rw0, *rw1, *rw2;     // resw3/5/9  [2][F][FF][K]
    const float *aw, *au, *gc1, *gc2, *f1;
    float *wA0, *wA1, *wA2;
    float *wB0, *wB1, *wB2, *wB3, *wB4, *wB5;
    float *awp, *aup, *gwt, *f1T;
};

__global__ void k_prep_all(PrepPtrs P) {
    int seg = blockIdx.y;
    int idx0 = blockIdx.x * 256 + threadIdx.x;
    int stride = gridDim.x * 256;
    if (seg < 3) {                       // wA: [K][DD][FP], CIN=DD
        int K = (seg == 0) ? 3 : (seg == 1) ? 5 : 9;
        const float* src = (seg == 0) ? P.cw0 : (seg == 1) ? P.cw1 : P.cw2;
        float* dst = (seg == 0) ? P.wA0 : (seg == 1) ? P.wA1 : P.wA2;
        int tot = K * DD * FP;
        for (int idx = idx0; idx < tot; idx += stride) {
            int f = idx & 127;
            int rem = idx >> 7;
            int d = rem % DD;
            int k = rem / DD;
            dst[idx] = (f < FF) ? to_tf32(src[(f * DD + d) * K + k]) : 0.f;
        }
    } else if (seg < 9) {                // wB: [K][FP][FP], CIN=FF
        int inst = seg - 3, br = inst >> 1, which = inst & 1;
        int K = (br == 0) ? 3 : (br == 1) ? 5 : 9;
        const float* base = (br == 0) ? P.rw0 : (br == 1) ? P.rw1 : P.rw2;
        const float* src = base + (size_t)which * FF * FF * K;
        float* dst = (inst == 0) ? P.wB0 : (inst == 1) ? P.wB1 : (inst == 2) ? P.wB2 :
                     (inst == 3) ? P.wB3 : (inst == 4) ? P.wB4 : P.wB5;
        int tot = K * FP * FP;
        for (int idx = idx0; idx < tot; idx += stride) {
            int f = idx & 127;
            int rem = idx >> 7;
            int d = rem % FP;
            int k = rem / FP;
            dst[idx] = (f < FF && d < FF) ? to_tf32(src[(f * FF + d) * K + k]) : 0.f;
        }
    } else if (seg < 12) {               // awp: Bt[k(FP)][a(AA)]
        int br = seg - 9;
        const float* src = P.aw + (size_t)br * AA * FF;
        float* dst = P.awp + (size_t)br * FP * AA;
        int tot = FP * AA;
        for (int idx = idx0; idx < tot; idx += stride) {
            int k = idx >> 8, n = idx & (AA - 1);
            dst[idx] = (k < FF) ? to_tf32(src[n * FF + k]) : 0.f;
        }
    } else if (seg < 15) {               // aup: Bt[k(AA)][c(64)]
        int br = seg - 12;
        const float* src = P.au + (size_t)br * CC * AA;
        float* dst = P.aup + (size_t)br * AA * 64;
        int tot = AA * 64;
        for (int idx = idx0; idx < tot; idx += stride) {
            int k = idx >> 6, n = idx & 63;
            dst[idx] = (n < CC) ? to_tf32(src[n * AA + k]) : 0.f;
        }
    } else if (seg < 17) {               // GCN weight transposes
        const float* src = (seg == 15) ? P.gc1 : P.gc2;
        float* dst = P.gwt + (size_t)(seg - 15) * DD * DD;
        int tot = DD * DD;
        for (int idx = idx0; idx < tot; idx += stride) {
            int k = idx >> 8, n = idx & (DD - 1);
            dst[idx] = to_tf32(src[n * DD + k]);
        }
    } else {                             // f1T
        int tot = FEAT * FFNH;
        for (int idx = idx0; idx < tot; idx += stride) {
            int h = idx & (FFNH - 1), k = idx >> 7;
            P.f1T[idx] = P.f1[h * FEAT + k];
        }
    }
}

// ---------------- conv1d 'same' via tf32 mma, cp.async + dbuf weights -------
template<int K, int CINP>
__global__ void __launch_bounds__(256, 2)
k_conv_mma(const float* __restrict__ in, const float* __restrict__ wT,
           const float* __restrict__ cb, const float* __restrict__ gamma,
           const float* __restrict__ beta, const float* __restrict__ resid,
           float* __restrict__ out, int mode) {
    constexpr int LT = 128;
    constexpr int PAD = K / 2;
    constexpr int ROWS = LT + K - 1;
    constexpr int ISTR = 36;
    constexpr int WSTR = 136;
    constexpr int WTILE = 32 * WSTR;
    extern __shared__ float smem[];
    float* s_in = smem;                 // ROWS*ISTR
    float* s_w  = smem + ROWS * ISTR;   // 2 * WTILE

    int b = blockIdx.y, l0 = blockIdx.x * LT, tid = threadIdx.x;
    int wid = tid >> 5, lane = tid & 31;
    int wl = wid >> 1, wf = wid & 1;
    int grp = lane >> 2, thr = lane & 3;

    float acc[2][8][4];
#pragma unroll
    for (int mi = 0; mi < 2; mi++)
#pragma unroll
        for (int ni = 0; ni < 8; ni++)
#pragma unroll
            for (int ci = 0; ci < 4; ci++) acc[mi][ni][ci] = 0.f;

    const float* inb = in + (size_t)b * LL * CINP;

    for (int d0 = 0; d0 < CINP; d0 += 32) {
        for (int t = tid; t < ROWS * 8; t += 256) {
            int row = t >> 3, seg = t & 7;
            int gl = l0 - PAD + row;
            cp16(&s_in[row * ISTR + seg * 4],
                 inb + (size_t)gl * CINP + d0 + seg * 4,
                 (gl >= 0 && gl < LL));
        }
        {
            const float* wk = wT + (size_t)d0 * FP;
            for (int t = tid; t < 32 * 32; t += 256) {
                int dd = t >> 5, seg = t & 31;
                cp16(&s_w[dd * WSTR + seg * 4], wk + dd * FP + seg * 4, true);
            }
        }
        cp_commit();
        cp_wait0();
        __syncthreads();
#pragma unroll
        for (int k = 0; k < K; k++) {
            if (k + 1 < K) {
                const float* wk = wT + ((size_t)(k + 1) * CINP + d0) * FP;
                float* dstw = s_w + ((k + 1) & 1) * WTILE;
                for (int t = tid; t < 32 * 32; t += 256) {
                    int dd = t >> 5, seg = t & 31;
                    cp16(&dstw[dd * WSTR + seg * 4], wk + dd * FP + seg * 4, true);
                }
                cp_commit();
            }
            const float* curw = s_w + (k & 1) * WTILE;
#pragma unroll
            for (int ds = 0; ds < 32; ds += 8) {
                uint32_t a[2][4];
#pragma unroll
                for (int mi = 0; mi < 2; mi++) {
                    int r0 = wl * 32 + mi * 16 + grp + k;
                    a[mi][0] = __float_as_uint(s_in[r0 * ISTR + ds + thr]);
                    a[mi][1] = __float_as_uint(s_in[(r0 + 8) * ISTR + ds + thr]);
                    a[mi][2] = __float_as_uint(s_in[r0 * ISTR + ds + thr + 4]);
                    a[mi][3] = __float_as_uint(s_in[(r0 + 8) * ISTR + ds + thr + 4]);
                }
#pragma unroll
                for (int ni = 0; ni < 8; ni++) {
                    int f = wf * 64 + ni * 8 + grp;
                    uint32_t b0 = __float_as_uint(curw[(ds + thr) * WSTR + f]);
                    uint32_t b1 = __float_as_uint(curw[(ds + thr + 4) * WSTR + f]);
                    mma8(acc[0][ni], a[0], b0, b1);
                    mma8(acc[1][ni], a[1], b0, b1);
                }
            }
            if (k + 1 < K) cp_wait0();
            __syncthreads();
        }
    }

    const float BNI = rsqrtf(1.f + 1e-5f);
#pragma unroll
    for (int mi = 0; mi < 2; mi++) {
#pragma unroll
        for (int ci = 0; ci < 4; ci++) {
            int l = l0 + wl * 32 + mi * 16 + grp + ((ci >= 2) ? 8 : 0);
            size_t base = ((size_t)b * LL + l) * FP;
#pragma unroll
            for (int ni = 0; ni < 8; ni++) {
                int f = wf * 64 + ni * 8 + 2 * thr + (ci & 1);
                float v = acc[mi][ni][ci];
                float o;
                if (f < FF) {
                    float sc = gamma[f] * BNI, bt = beta[f];
                    if (mode == 0) o = tanhf(v + cb[f]) * sc + bt;
                    else           o = tanhf(v * sc + bt + resid[base + f]);
                    o = to_tf32(o);
                } else {
                    o = 0.f;
                }
                out[base + f] = o;
            }
        }
    }
}

template<int K, int CINP>
constexpr int conv_smem_bytes() {
    return ((128 + K - 1) * 36 + 2 * 32 * 136) * 4;
}

// ---------------- generic tf32 NT GEMM: out[m][n] = A[m][k]*Bt[k][n] --------
template<int CINP, int WF, bool TANH, bool TRANSOUT>
__global__ void k_mma_nt(const float* __restrict__ A, const float* __restrict__ Bt,
                         float* __restrict__ out, int nstride,
                         size_t a_bstr, size_t o_bstr, int ostr, int cclamp) {
    constexpr int NT = WF * 128;           // threads
    constexpr int WIDTH = WF * 64;         // n-tile
    constexpr int WSTR = WIDTH + 8;
    __shared__ float s_a[128 * 36];
    __shared__ float s_w[32 * WSTR];
    int b = blockIdx.z;
    int m0 = blockIdx.x * 128;
    int n0 = blockIdx.y * WIDTH;
    A += (size_t)b * a_bstr;
    out += (size_t)b * o_bstr;
    int tid = threadIdx.x;
    int wid = tid >> 5, lane = tid & 31;
    int wl = wid / WF, wf = wid % WF;
    int grp = lane >> 2, thr = lane & 3;

    float acc[2][8][4];
#pragma unroll
    for (int mi = 0; mi < 2; mi++)
#pragma unroll
        for (int ni = 0; ni < 8; ni++)
#pragma unroll
            for (int ci = 0; ci < 4; ci++) acc[mi][ni][ci] = 0.f;

    for (int k0 = 0; k0 < CINP; k0 += 32) {
        __syncthreads();
        for (int t = tid; t < 128 * 8; t += NT) {
            int row = t >> 3, seg = t & 7;
            cp16(&s_a[row * 36 + seg * 4],
                 A + (size_t)(m0 + row) * CINP + k0 + seg * 4, true);
        }
        for (int t = tid; t < 32 * (WIDTH / 4); t += NT) {
            int dd = t / (WIDTH / 4), seg = t % (WIDTH / 4);
            cp16(&s_w[dd * WSTR + seg * 4],
                 Bt + (size_t)(k0 + dd) * nstride + n0 + seg * 4, true);
        }
        cp_commit();
        cp_wait0();
        __syncthreads();
#pragma unroll
        for (int ds = 0; ds < 32; ds += 8) {
            uint32_t a[2][4];
#pragma unroll
            for (int mi = 0; mi < 2; mi++) {
                int r0 = wl * 32 + mi * 16 + grp;
                a[mi][0] = __float_as_uint(s_a[r0 * 36 + ds + thr]);
                a[mi][1] = __float_as_uint(s_a[(r0 + 8) * 36 + ds + thr]);
                a[mi][2] = __float_as_uint(s_a[r0 * 36 + ds + thr + 4]);
                a[mi][3] = __float_as_uint(s_a[(r0 + 8) * 36 + ds + thr + 4]);
            }
#pragma unroll
            for (int ni = 0; ni < 8; ni++) {
                int f = wf * 64 + ni * 8 + grp;
                uint32_t b0 = __float_as_uint(s_w[(ds + thr) * WSTR + f]);
                uint32_t b1 = __float_as_uint(s_w[(ds + thr + 4) * WSTR + f]);
                mma8(acc[0][ni], a[0], b0, b1);
                mma8(acc[1][ni], a[1], b0, b1);
            }
        }
    }

#pragma unroll
    for (int mi = 0; mi < 2; mi++) {
#pragma unroll
        for (int ci = 0; ci < 4; ci++) {
            int mrow = wl * 32 + mi * 16 + grp + ((ci >= 2) ? 8 : 0);
#pragma unroll
            for (int ni = 0; ni < 8; ni++) {
                int n = wf * 64 + ni * 8 + 2 * thr + (ci & 1);
                float v = acc[mi][ni][ci];
                if (TANH) v = to_tf32(tanhf(v));
                if (TRANSOUT) {
                    int c = n0 + n;
                    if (c < cclamp) out[(size_t)c * LL + m0 + mrow] = v;
                } else {
                    out[(size_t)(m0 + mrow) * ostr + n0 + n] = v;
                }
            }
        }
    }
}

// ---------------- softmax stats per (b,c) row of length L -------------------
__global__ void k_soft(const float* __restrict__ logits, float* __restrict__ rmax,
                       float* __restrict__ rsinv) {
    __shared__ float sred[256];
    int c = blockIdx.x, b = blockIdx.y, tid = threadIdx.x;
    const float* row = logits + ((size_t)b * CC + c) * LL;
    float m = -1e30f;
    for (int l = tid; l < LL; l += 256) m = fmaxf(m, row[l]);
    sred[tid] = m; __syncthreads();
    for (int s = 128; s > 0; s >>= 1) {
        if (tid < s) sred[tid] = fmaxf(sred[tid], sred[tid + s]);
        __syncthreads();
    }
    m = sred[0]; __syncthreads();
    float sum = 0.f;
    for (int l = tid; l < LL; l += 256) sum += expf(row[l] - m);
    sred[tid] = sum; __syncthreads();
    for (int s = 128; s > 0; s >>= 1) {
        if (tid < s) sred[tid] += sred[tid + s];
        __syncthreads();
    }
    if (tid == 0) { rmax[b * CC + c] = m; rsinv[b * CC + c] = 1.f / sred[0]; }
}

// ---------------- V partials: vpart[chunk][b][c][f] -------------------------
__global__ void k_v(const float* __restrict__ t, const float* __restrict__ logits,
                    const float* __restrict__ rmax, const float* __restrict__ rsinv,
                    float* __restrict__ vpart) {
    __shared__ float s_w[25][256];
    int cgrp = blockIdx.x, chunk = blockIdx.y, b = blockIdx.z;
    int tid = threadIdx.x;                 // 128 threads
    int l0 = chunk * 256;
    for (int idx = tid; idx < 25 * 256; idx += 128) {
        int cl = idx >> 8, ll = idx & 255;
        int c = cgrp * 25 + cl;
        float m = rmax[b * CC + c], si = rsinv[b * CC + c];
        s_w[cl][ll] = expf(logits[((size_t)b * CC + c) * LL + l0 + ll] - m) * si;
    }
    __syncthreads();
    float acc[25];
#pragma unroll
    for (int c = 0; c < 25; c++) acc[c] = 0.f;
    int f = tid;
    for (int ll = 0; ll < 256; ll++) {
        float tv = (f < FF) ? t[((size_t)b * LL + l0 + ll) * FP + f] : 0.f;
#pragma unroll
        for (int c = 0; c < 25; c++) acc[c] += s_w[c][ll] * tv;
    }
    if (f < FF) {
#pragma unroll
        for (int c = 0; c < 25; c++) {
            int cg = cgrp * 25 + c;
            vpart[(((size_t)chunk * BB + b) * CC + cg) * FF + f] = acc[c];
        }
    }
}

__global__ void k_vred(const float* __restrict__ vpart, float* __restrict__ V) {
    int idx = blockIdx.x * 256 + threadIdx.x;
    if (idx >= BB * CC * FF) return;
    float s = 0.f;
#pragma unroll
    for (int ch = 0; ch < 16; ch++) s += vpart[(size_t)ch * BB * CC * FF + idx];
    V[idx] = s;
}

// ---------------- GCN ------------------------------------------------------
__global__ void k_nodes(const int* __restrict__ nodes, const float* __restrict__ emb,
                        float* __restrict__ xn) {
    size_t idx = (size_t)blockIdx.x * 256 + threadIdx.x;
    if (idx >= (size_t)BB * NN * DD) return;
    int d = (int)(idx & (DD - 1));
    size_t row = idx >> 8;
    xn[idx] = to_tf32(emb[(size_t)nodes[row] * DD + d]);
}

__global__ void k_deginit(int* __restrict__ deg) {
    int idx = blockIdx.x * 256 + threadIdx.x;
    if (idx < BB * NN) deg[idx] = 1;   // self loop
}

__global__ void k_degadd(const int* __restrict__ edges, int* __restrict__ deg) {
    int idx = blockIdx.x * 256 + threadIdx.x;
    if (idx >= BB * EE) return;
    int b = idx / EE, e = idx % EE;
    int dst = edges[(b * 2 + 1) * EE + e];
    atomicAdd(&deg[b * NN + dst], 1);
}

__global__ void k_dinv(const int* __restrict__ deg, float* __restrict__ dinv) {
    int idx = blockIdx.x * 256 + threadIdx.x;
    if (idx < BB * NN) dinv[idx] = rsqrtf((float)deg[idx]);
}

__global__ void k_self(const float* __restrict__ xw, const float* __restrict__ dinv,
                       float* __restrict__ out, int rows) {
    size_t idx = (size_t)blockIdx.x * 256 + threadIdx.x;
    if (idx >= (size_t)BB * rows * DD) return;
    int o = (int)(idx & (DD - 1));
    size_t row = idx >> 8;
    int b = (int)(row / rows);
    int n = (int)(row % rows);
    float di = dinv[b * NN + n];
    out[idx] = di * di * xw[((size_t)b * NN + n) * DD + o];
}

__global__ void k_edge(const int* __restrict__ edges, const float* __restrict__ dinv,
                       const float* __restrict__ xw, float* __restrict__ out,
                       int dstmax) {
    int b = blockIdx.y;
    int eloc = threadIdx.x >> 5, lane = threadIdx.x & 31;
    int e = blockIdx.x * 8 + eloc;
    int src = edges[(b * 2) * EE + e];
    int dst = edges[(b * 2 + 1) * EE + e];
    if (dst >= dstmax) return;
    float norm = dinv[b * NN + src] * dinv[b * NN + dst];
    const float* xr = xw + ((size_t)b * NN + src) * DD;
    float* orow = out + ((size_t)b * dstmax + dst) * DD;
#pragma unroll
    for (int j = 0; j < 8; j++) {
        int o = lane + j * 32;
        atomicAdd(&orow[o], norm * xr[o]);
    }
}

__global__ void k_post(float* __restrict__ buf, const float* __restrict__ bias,
                       int rows, int dorelu) {
    size_t idx = (size_t)blockIdx.x * 256 + threadIdx.x;
    if (idx >= (size_t)BB * rows * DD) return;
    int o = (int)(idx & (DD - 1));
    float v = buf[idx] + bias[o];
    if (dorelu) v = fmaxf(v, 0.f);
    buf[idx] = to_tf32(v);
}

// ---------------- final MLP --------------------------------------------------
__global__ void k_final(const float* __restrict__ gout, const float* __restrict__ V,
                        const float* __restrict__ f1T, const float* __restrict__ f1b,
                        const float* __restrict__ f2w, const float* __restrict__ f2b,
                        float* __restrict__ y) {
    __shared__ float s_feat[FEAT];
    __shared__ float s_red[FFNH];
    int c = blockIdx.x, b = blockIdx.y, h = threadIdx.x;   // 128 threads
    for (int idx = h; idx < FEAT; idx += FFNH) {
        float v;
        if (idx < DD) {
            v = gout[((size_t)b * CC + c) * DD + idx];
        } else {
            int br = (idx - DD) / FF;
            int f  = (idx - DD) % FF;
            v = V[(((size_t)br * BB + b) * CC + c) * FF + f];
        }
        s_feat[idx] = v;
    }
    __syncthreads();
    float acc = f1b[h];
    for (int k = 0; k < FEAT; k++) acc += f1T[k * FFNH + h] * s_feat[k];
    float hid = fmaxf(acc, 0.f);
    s_red[h] = f2w[c * FFNH + h] * hid;
    __syncthreads();
    for (int s = 64; s > 0; s >>= 1) {
        if (h < s) s_red[h] += s_red[h + s];
        __syncthreads();
    }
    if (h == 0) y[b * CC + c] = s_red[0] + f2b[c];
}

// ---------------- branch driver (preps already done) -------------------------
template<int K>
static void run_branch(const float* cb, const float* bn_g, const float* bn_b,
                       float* buf, int br,
                       float* wA, float* wB0, float* wB1) {
    float* h    = buf + OFF_H;
    float* t0   = buf + OFF_T0;
    float* t1   = buf + OFF_T1;
    float* Z    = buf + OFF_Z;
    float* lg   = buf + OFF_LOG;
    float* rmax = buf + OFF_RMAX;
    float* rsin = buf + OFF_RSINV;
    float* vp   = buf + OFF_VPART;
    float* V    = buf + OFF_V + (size_t)br * BB * CC * FF;
    float* awp  = buf + OFF_AWP + (size_t)br * FP * AA;
    float* aup  = buf + OFF_AUP + (size_t)br * AA * 64;

    cudaFuncSetAttribute(k_conv_mma<K, DD>, cudaFuncAttributeMaxDynamicSharedMemorySize,
                         conv_smem_bytes<K, DD>());
    cudaFuncSetAttribute(k_conv_mma<K, FP>, cudaFuncAttributeMaxDynamicSharedMemorySize,
                         conv_smem_bytes<K, FP>());

    dim3 cgrid(LL / 128, BB);
    k_conv_mma<K, DD><<<cgrid, 256, conv_smem_bytes<K, DD>()>>>(
        h, wA, cb, bn_g, bn_b, nullptr, t0, 0);
    k_conv_mma<K, FP><<<cgrid, 256, conv_smem_bytes<K, FP>()>>>(
        t0, wB0, nullptr, bn_g + FF, bn_b + FF, t0, t1, 1);
    k_conv_mma<K, FP><<<cgrid, 256, conv_smem_bytes<K, FP>()>>>(
        t1, wB1, nullptr, bn_g + 2 * FF, bn_b + 2 * FF, t1, t0, 1);

    // Z[b][l][a] = tanh(t0 . aw^T)
    k_mma_nt<FP, 2, true, false><<<dim3(LL / 128, AA / 128, BB), 256>>>(
        t0, awp, Z, AA, (size_t)LL * FP, (size_t)LL * AA, AA, 0);
    // logits[b][c][l] = Z . au^T (transposed store)
    k_mma_nt<AA, 1, false, true><<<dim3(LL / 128, 1, BB), 128>>>(
        Z, aup, lg, 64, (size_t)LL * AA, (size_t)CC * LL, 0, CC);

    k_soft<<<dim3(CC, BB), 256>>>(lg, rmax, rsin);
    k_v<<<dim3(2, 16, BB), 128>>>(t0, lg, rmax, rsin, vp);
    k_vred<<<(BB * CC * FF + 255) / 256, 256>>>(vp, V);
}

extern "C" void kernel_launch(void* const* d_in, const int* in_sizes, int n_in,
                              void* d_out, int out_size) {
    const int*   x        = (const int*)d_in[0];
    const int*   nodes    = (const int*)d_in[2];
    const int*   edges    = (const int*)d_in[3];
    const float* word_emb = (const float*)d_in[4];
    const float* ent_emb  = (const float*)d_in[5];
    const float* convw3   = (const float*)d_in[6];
    const float* convb3   = (const float*)d_in[7];
    const float* resw3    = (const float*)d_in[8];
    const float* convw5   = (const float*)d_in[9];
    const float* convb5   = (const float*)d_in[10];
    const float* resw5    = (const float*)d_in[11];
    const float* convw9   = (const float*)d_in[12];
    const float* convb9   = (const float*)d_in[13];
    const float* resw9    = (const float*)d_in[14];
    const float* bn_gamma = (const float*)d_in[15];
    const float* bn_beta  = (const float*)d_in[16];
    const float* attn_w   = (const float*)d_in[17];
    const float* attn_u   = (const float*)d_in[18];
    const float* gc1_w    = (const float*)d_in[19];
    const float* gc1_b    = (const float*)d_in[20];
    const float* gc2_w    = (const float*)d_in[21];
    const float* gc2_b    = (const float*)d_in[22];
    const float* fin1_w   = (const float*)d_in[23];
    const float* fin1_b   = (const float*)d_in[24];
    const float* fin2_w   = (const float*)d_in[25];
    const float* fin2_b   = (const float*)d_in[26];
    float* out = (float*)d_out;

    float* buf; int* deg;
    cudaGetSymbolAddress((void**)&buf, g_buf);
    cudaGetSymbolAddress((void**)&deg, g_deg);

    float* wA = buf + OFF_WA;
    float* wB = buf + OFF_WB;
    const size_t wA_off[3] = {0, 3 * (size_t)DD * FP, 8 * (size_t)DD * FP};
    const size_t wB_off[6] = {0, 3 * (size_t)FP * FP,
                              6 * (size_t)FP * FP, 11 * (size_t)FP * FP,
                              16 * (size_t)FP * FP, 25 * (size_t)FP * FP};

    PrepPtrs P;
    P.cw0 = convw3; P.cw1 = convw5; P.cw2 = convw9;
    P.rw0 = resw3;  P.rw1 = resw5;  P.rw2 = resw9;
    P.aw = attn_w;  P.au = attn_u;
    P.gc1 = gc1_w;  P.gc2 = gc2_w;  P.f1 = fin1_w;
    P.wA0 = wA + wA_off[0]; P.wA1 = wA + wA_off[1]; P.wA2 = wA + wA_off[2];
    P.wB0 = wB + wB_off[0]; P.wB1 = wB + wB_off[1]; P.wB2 = wB + wB_off[2];
    P.wB3 = wB + wB_off[3]; P.wB4 = wB + wB_off[4]; P.wB5 = wB + wB_off[5];
    P.awp = buf + OFF_AWP; P.aup = buf + OFF_AUP;
    P.gwt = buf + OFF_GWT; P.f1T = buf + OFF_F1T;

    // launch 1: embed; 2: all preps; 3: deg init; 4: conv<9,256> (profiled)
    k_embed<<<(int)(((size_t)BB * LL * DD + 255) / 256), 256>>>(x, word_emb, buf + OFF_H);
    k_prep_all<<<dim3(1152, 18), 256>>>(P);
    k_deginit<<<(BB * NN + 255) / 256, 256>>>(deg);

    run_branch<9>(convb9, bn_gamma + 2 * 3 * FF, bn_beta + 2 * 3 * FF, buf, 2,
                  wA + wA_off[2], wB + wB_off[4], wB + wB_off[5]);
    run_branch<3>(convb3, bn_gamma + 0 * 3 * FF, bn_beta + 0 * 3 * FF, buf, 0,
                  wA + wA_off[0], wB + wB_off[0], wB + wB_off[1]);
    run_branch<5>(convb5, bn_gamma + 1 * 3 * FF, bn_beta + 1 * 3 * FF, buf, 1,
                  wA + wA_off[1], wB + wB_off[2], wB + wB_off[3]);

    // GCN
    float* xn   = buf + OFF_XN;
    float* xw   = buf + OFF_XW;
    float* g1   = buf + OFF_G1;
    float* gout = buf + OFF_GOUT;
    float* dinv = buf + OFF_DINV;
    float* gwt1 = buf + OFF_GWT;
    float* gwt2 = buf + OFF_GWT + (size_t)DD * DD;
    k_nodes<<<(int)(((size_t)BB * NN * DD + 255) / 256), 256>>>(nodes, ent_emb, xn);
    k_degadd<<<(BB * EE + 255) / 256, 256>>>(edges, deg);
    k_dinv<<<(BB * NN + 255) / 256, 256>>>(deg, dinv);

    k_mma_nt<DD, 2, false, false><<<dim3(NN / 128, DD / 128, BB), 256>>>(
        xn, gwt1, xw, DD, (size_t)NN * DD, (size_t)NN * DD, DD, 0);
    k_self<<<(int)(((size_t)BB * NN * DD + 255) / 256), 256>>>(xw, dinv, g1, NN);
    k_edge<<<dim3(EE / 8, BB), 256>>>(edges, dinv, xw, g1, NN);
    k_post<<<(int)(((size_t)BB * NN * DD + 255) / 256), 256>>>(g1, gc1_b, NN, 1);

    k_mma_nt<DD, 2, false, false><<<dim3(NN / 128, DD / 128, BB), 256>>>(
        g1, gwt2, xw, DD, (size_t)NN * DD, (size_t)NN * DD, DD, 0);
    k_self<<<(int)(((size_t)BB * CC * DD + 255) / 256), 256>>>(xw, dinv, gout, CC);
    k_edge<<<dim3(EE / 8, BB), 256>>>(edges, dinv, xw, gout, CC);
    k_post<<<(int)(((size_t)BB * CC * DD + 255) / 256), 256>>>(gout, gc2_b, CC, 0);

    // final MLP
    k_final<<<dim3(CC, BB), FFNH>>>(gout, buf + OFF_V, buf + OFF_F1T,
                                    fin1_b, fin2_w, fin2_b, out);
}

// round 14
// speedup vs baseline: 1.4053x; 1.1601x over previous
#include <cuda_runtime.h>
#include <math.h>
#include <stdint.h>

#define BB   16
#define LL   4096
#define DD   256
#define CC   50
#define NN   512
#define EE   8192
#define FF   100
#define FP   128
#define AA   256
#define FFNH 128
#define FEAT 556   /* 256 + 3*100 */

static constexpr size_t T0SZ  = (size_t)BB*LL*FP;
static constexpr size_t ZSZ   = (size_t)BB*LL*AA;
static constexpr size_t LOGSZ = (size_t)BB*CC*LL;
static constexpr size_t VPSZ  = (size_t)16*BB*CC*FF;
static constexpr size_t VSZ   = (size_t)BB*CC*FF;

// ---------------- one big static scratch buffer (no allocations) ------------
static constexpr size_t OFF_H     = 0;
static constexpr size_t OFF_T0    = OFF_H     + (size_t)BB*LL*DD;
static constexpr size_t OFF_T1    = OFF_T0    + 3*T0SZ;
static constexpr size_t OFF_Z     = OFF_T1    + 3*T0SZ;
static constexpr size_t OFF_LOG   = OFF_Z     + 3*ZSZ;
static constexpr size_t OFF_RMAX  = OFF_LOG   + 3*LOGSZ;
static constexpr size_t OFF_RSINV = OFF_RMAX  + (size_t)3*BB*CC;
static constexpr size_t OFF_VPART = OFF_RSINV + (size_t)3*BB*CC;
static constexpr size_t OFF_V     = OFF_VPART + 3*VPSZ;
static constexpr size_t OFF_WA    = OFF_V     + 3*VSZ;
static constexpr size_t OFF_WB    = OFF_WA    + (size_t)3*9*DD*FP;
static constexpr size_t OFF_AWP   = OFF_WB    + (size_t)6*9*FP*FP;
static constexpr size_t OFF_AUP   = OFF_AWP   + (size_t)3*FP*AA;
static constexpr size_t OFF_GWT   = OFF_AUP   + (size_t)3*AA*64;
static constexpr size_t OFF_XN    = OFF_GWT   + (size_t)2*DD*DD;
static constexpr size_t OFF_XW    = OFF_XN    + (size_t)BB*NN*DD;
static constexpr size_t OFF_G1    = OFF_XW    + (size_t)BB*NN*DD;
static constexpr size_t OFF_GOUT  = OFF_G1    + (size_t)BB*NN*DD;
static constexpr size_t OFF_F1T   = OFF_GOUT  + (size_t)BB*CC*DD;
static constexpr size_t OFF_DINV  = OFF_F1T   + (size_t)FEAT*FFNH;
static constexpr size_t BUF_TOTAL = OFF_DINV  + (size_t)BB*NN;

__device__ float g_buf[BUF_TOTAL];
__device__ int   g_deg[BB*NN];

// ---------------- helpers ----------------------------------------------------
__device__ __forceinline__ float to_tf32(float x) {
    float r;
    asm("cvt.rna.tf32.f32 %0, %1;" : "=f"(r) : "f"(x));
    return r;
}

__device__ __forceinline__ void mma8(float d[4], const uint32_t a[4],
                                     uint32_t b0, uint32_t b1) {
    asm volatile(
        "mma.sync.aligned.m16n8k8.row.col.f32.tf32.tf32.f32 "
        "{%0,%1,%2,%3}, {%4,%5,%6,%7}, {%8,%9}, {%0,%1,%2,%3};\n"
        : "+f"(d[0]), "+f"(d[1]), "+f"(d[2]), "+f"(d[3])
        : "r"(a[0]), "r"(a[1]), "r"(a[2]), "r"(a[3]), "r"(b0), "r"(b1));
}

__device__ __forceinline__ void cp16(float* dst_smem, const float* src, bool pred) {
    uint32_t d = (uint32_t)__cvta_generic_to_shared(dst_smem);
    int sz = pred ? 16 : 0;
    asm volatile("cp.async.cg.shared.global [%0], [%1], 16, %2;\n"
                 :: "r"(d), "l"(src), "r"(sz));
}
__device__ __forceinline__ void cp_commit() {
    asm volatile("cp.async.commit_group;\n");
}
__device__ __forceinline__ void cp_wait0() {
    asm volatile("cp.async.wait_group 0;\n");
}

// ---------------- embedding gather  h[b][l][d] (tf32-rounded) ----------------
__global__ void k_embed(const int* __restrict__ x, const float* __restrict__ emb,
                        float* __restrict__ h) {
    size_t idx = (size_t)blockIdx.x * 256 + threadIdx.x;
    if (idx >= (size_t)BB*LL*DD) return;
    int d = (int)(idx & (DD - 1));
    size_t row = idx >> 8;
    h[idx] = to_tf32(emb[(size_t)x[row] * DD + d]);
}

// ---------------- merged prep kernel (18 segments) ---------------------------
struct PrepPtrs {
    const float *cw0, *cw1, *cw2;     // convw3/5/9 [F][DD][K]
    const float *rw0, *rw1, *rw2;     // resw3/5/9  [2][F][FF][K]
    const float *aw, *au, *gc1, *gc2, *f1;
    float *wA0, *wA1, *wA2;
    float *wB0, *wB1, *wB2, *wB3, *wB4, *wB5;
    float *awp, *aup, *gwt, *f1T;
};

__global__ void k_prep_all(PrepPtrs P) {
    int seg = blockIdx.y;
    int idx0 = blockIdx.x * 256 + threadIdx.x;
    int stride = gridDim.x * 256;
    if (seg < 3) {                       // wA: [K][DD][FP], CIN=DD
        int K = (seg == 0) ? 3 : (seg == 1) ? 5 : 9;
        const float* src = (seg == 0) ? P.cw0 : (seg == 1) ? P.cw1 : P.cw2;
        float* dst = (seg == 0) ? P.wA0 : (seg == 1) ? P.wA1 : P.wA2;
        int tot = K * DD * FP;
        for (int idx = idx0; idx < tot; idx += stride) {
            int f = idx & 127;
            int rem = idx >> 7;
            int d = rem % DD;
            int k = rem / DD;
            dst[idx] = (f < FF) ? to_tf32(src[(f * DD + d) * K + k]) : 0.f;
        }
    } else if (seg < 9) {                // wB: [K][FP][FP], CIN=FF
        int inst = seg - 3, br = inst >> 1, which = inst & 1;
        int K = (br == 0) ? 3 : (br == 1) ? 5 : 9;
        const float* base = (br == 0) ? P.rw0 : (br == 1) ? P.rw1 : P.rw2;
        const float* src = base + (size_t)which * FF * FF * K;
        float* dst = (inst == 0) ? P.wB0 : (inst == 1) ? P.wB1 : (inst == 2) ? P.wB2 :
                     (inst == 3) ? P.wB3 : (inst == 4) ? P.wB4 : P.wB5;
        int tot = K * FP * FP;
        for (int idx = idx0; idx < tot; idx += stride) {
            int f = idx & 127;
            int rem = idx >> 7;
            int d = rem % FP;
            int k = rem / FP;
            dst[idx] = (f < FF && d < FF) ? to_tf32(src[(f * FF + d) * K + k]) : 0.f;
        }
    } else if (seg < 12) {               // awp: Bt[k(FP)][a(AA)]
        int br = seg - 9;
        const float* src = P.aw + (size_t)br * AA * FF;
        float* dst = P.awp + (size_t)br * FP * AA;
        int tot = FP * AA;
        for (int idx = idx0; idx < tot; idx += stride) {
            int k = idx >> 8, n = idx & (AA - 1);
            dst[idx] = (k < FF) ? to_tf32(src[n * FF + k]) : 0.f;
        }
    } else if (seg < 15) {               // aup: Bt[k(AA)][c(64)]
        int br = seg - 12;
        const float* src = P.au + (size_t)br * CC * AA;
        float* dst = P.aup + (size_t)br * AA * 64;
        int tot = AA * 64;
        for (int idx = idx0; idx < tot; idx += stride) {
            int k = idx >> 6, n = idx & 63;
            dst[idx] = (n < CC) ? to_tf32(src[n * AA + k]) : 0.f;
        }
    } else if (seg < 17) {               // GCN weight transposes
        const float* src = (seg == 15) ? P.gc1 : P.gc2;
        float* dst = P.gwt + (size_t)(seg - 15) * DD * DD;
        int tot = DD * DD;
        for (int idx = idx0; idx < tot; idx += stride) {
            int k = idx >> 8, n = idx & (DD - 1);
            dst[idx] = to_tf32(src[n * DD + k]);
        }
    } else {                             // f1T
        int tot = FEAT * FFNH;
        for (int idx = idx0; idx < tot; idx += stride) {
            int h = idx & (FFNH - 1), k = idx >> 7;
            P.f1T[idx] = P.f1[h * FEAT + k];
        }
    }
}

// ---------------- conv body (R6-proven), inlined per-K --------------------
template<int K, int CINP>
__device__ __forceinline__ void conv_body(
    const float* __restrict__ in, const float* __restrict__ wT,
    const float* __restrict__ cb, const float* __restrict__ gamma,
    const float* __restrict__ beta, const float* __restrict__ resid,
    float* __restrict__ out, int mode, float* smem) {
    constexpr int LT = 128;
    constexpr int PAD = K / 2;
    constexpr int ROWS = LT + K - 1;
    constexpr int ISTR = 36;
    constexpr int WSTR = 136;
    constexpr int WTILE = 32 * WSTR;
    float* s_in = smem;
    float* s_w  = smem + ROWS * ISTR;

    int b = blockIdx.y, l0 = blockIdx.x * LT, tid = threadIdx.x;
    int wid = tid >> 5, lane = tid & 31;
    int wl = wid >> 1, wf = wid & 1;
    int grp = lane >> 2, thr = lane & 3;

    float acc[2][8][4];
#pragma unroll
    for (int mi = 0; mi < 2; mi++)
#pragma unroll
        for (int ni = 0; ni < 8; ni++)
#pragma unroll
            for (int ci = 0; ci < 4; ci++) acc[mi][ni][ci] = 0.f;

    const float* inb = in + (size_t)b * LL * CINP;

    for (int d0 = 0; d0 < CINP; d0 += 32) {
        for (int t = tid; t < ROWS * 8; t += 256) {
            int row = t >> 3, seg = t & 7;
            int gl = l0 - PAD + row;
            cp16(&s_in[row * ISTR + seg * 4],
                 inb + (size_t)gl * CINP + d0 + seg * 4,
                 (gl >= 0 && gl < LL));
        }
        {
            const float* wk = wT + (size_t)d0 * FP;
            for (int t = tid; t < 32 * 32; t += 256) {
                int dd = t >> 5, seg = t & 31;
                cp16(&s_w[dd * WSTR + seg * 4], wk + dd * FP + seg * 4, true);
            }
        }
        cp_commit();
        cp_wait0();
        __syncthreads();
#pragma unroll
        for (int k = 0; k < K; k++) {
            if (k + 1 < K) {
                const float* wk = wT + ((size_t)(k + 1) * CINP + d0) * FP;
                float* dstw = s_w + ((k + 1) & 1) * WTILE;
                for (int t = tid; t < 32 * 32; t += 256) {
                    int dd = t >> 5, seg = t & 31;
                    cp16(&dstw[dd * WSTR + seg * 4], wk + dd * FP + seg * 4, true);
                }
                cp_commit();
            }
            const float* curw = s_w + (k & 1) * WTILE;
#pragma unroll
            for (int ds = 0; ds < 32; ds += 8) {
                uint32_t a[2][4];
#pragma unroll
                for (int mi = 0; mi < 2; mi++) {
                    int r0 = wl * 32 + mi * 16 + grp + k;
                    a[mi][0] = __float_as_uint(s_in[r0 * ISTR + ds + thr]);
                    a[mi][1] = __float_as_uint(s_in[(r0 + 8) * ISTR + ds + thr]);
                    a[mi][2] = __float_as_uint(s_in[r0 * ISTR + ds + thr + 4]);
                    a[mi][3] = __float_as_uint(s_in[(r0 + 8) * ISTR + ds + thr + 4]);
                }
#pragma unroll
                for (int ni = 0; ni < 8; ni++) {
                    int f = wf * 64 + ni * 8 + grp;
                    uint32_t b0 = __float_as_uint(curw[(ds + thr) * WSTR + f]);
                    uint32_t b1 = __float_as_uint(curw[(ds + thr + 4) * WSTR + f]);
                    mma8(acc[0][ni], a[0], b0, b1);
                    mma8(acc[1][ni], a[1], b0, b1);
                }
            }
            if (k + 1 < K) cp_wait0();
            __syncthreads();
        }
    }

    const float BNI = rsqrtf(1.f + 1e-5f);
#pragma unroll
    for (int mi = 0; mi < 2; mi++) {
#pragma unroll
        for (int ci = 0; ci < 4; ci++) {
            int l = l0 + wl * 32 + mi * 16 + grp + ((ci >= 2) ? 8 : 0);
            size_t base = ((size_t)b * LL + l) * FP;
#pragma unroll
            for (int ni = 0; ni < 8; ni++) {
                int f = wf * 64 + ni * 8 + 2 * thr + (ci & 1);
                float v = acc[mi][ni][ci];
                float o;
                if (f < FF) {
                    float sc = gamma[f] * BNI, bt = beta[f];
                    if (mode == 0) o = tanhf(v + cb[f]) * sc + bt;
                    else           o = tanhf(v * sc + bt + resid[base + f]);
                    o = to_tf32(o);
                } else {
                    o = 0.f;
                }
                out[base + f] = o;
            }
        }
    }
}

// Merged 3-branch conv: z=0 -> K9, z=1 -> K5, z=2 -> K3 (heavy first)
struct ConvMulti {
    const float* in[3];
    const float* wT[3];
    const float* cb[3];
    const float* gma[3];
    const float* bta[3];
    const float* resid[3];
    float* out[3];
    int mode;
};

template<int CINP>
__global__ void __launch_bounds__(256, 2) k_conv_multi(ConvMulti A) {
    extern __shared__ float smem[];
    int s = blockIdx.z;
    if (s == 0)
        conv_body<9, CINP>(A.in[0], A.wT[0], A.cb[0], A.gma[0], A.bta[0],
                           A.resid[0], A.out[0], A.mode, smem);
    else if (s == 1)
        conv_body<5, CINP>(A.in[1], A.wT[1], A.cb[1], A.gma[1], A.bta[1],
                           A.resid[1], A.out[1], A.mode, smem);
    else
        conv_body<3, CINP>(A.in[2], A.wT[2], A.cb[2], A.gma[2], A.bta[2],
                           A.resid[2], A.out[2], A.mode, smem);
}

static constexpr int conv_multi_smem() {
    return ((128 + 9 - 1) * 36 + 2 * 32 * 136) * 4;   // max over K
}

// ---------------- generic tf32 NT GEMM bodies -------------------------------
template<int CINP, int WF, bool TANH, bool TRANSOUT>
__device__ __forceinline__ void mma_nt_body(
    const float* __restrict__ A, const float* __restrict__ Bt,
    float* __restrict__ out, int nstride, int ostr, int cclamp) {
    constexpr int NT = WF * 128;
    constexpr int WIDTH = WF * 64;
    constexpr int WSTR = WIDTH + 8;
    __shared__ float s_a[128 * 36];
    __shared__ float s_w[32 * WSTR];
    int m0 = blockIdx.x * 128;
    int n0 = blockIdx.y * WIDTH;
    int tid = threadIdx.x;
    int wid = tid >> 5, lane = tid & 31;
    int wl = wid / WF, wf = wid % WF;
    int grp = lane >> 2, thr = lane & 3;

    float acc[2][8][4];
#pragma unroll
    for (int mi = 0; mi < 2; mi++)
#pragma unroll
        for (int ni = 0; ni < 8; ni++)
#pragma unroll
            for (int ci = 0; ci < 4; ci++) acc[mi][ni][ci] = 0.f;

    for (int k0 = 0; k0 < CINP; k0 += 32) {
        __syncthreads();
        for (int t = tid; t < 128 * 8; t += NT) {
            int row = t >> 3, seg = t & 7;
            cp16(&s_a[row * 36 + seg * 4],
                 A + (size_t)(m0 + row) * CINP + k0 + seg * 4, true);
        }
        for (int t = tid; t < 32 * (WIDTH / 4); t += NT) {
            int dd = t / (WIDTH / 4), seg = t % (WIDTH / 4);
            cp16(&s_w[dd * WSTR + seg * 4],
                 Bt + (size_t)(k0 + dd) * nstride + n0 + seg * 4, true);
        }
        cp_commit();
        cp_wait0();
        __syncthreads();
#pragma unroll
        for (int ds = 0; ds < 32; ds += 8) {
            uint32_t a[2][4];
#pragma unroll
            for (int mi = 0; mi < 2; mi++) {
                int r0 = wl * 32 + mi * 16 + grp;
                a[mi][0] = __float_as_uint(s_a[r0 * 36 + ds + thr]);
                a[mi][1] = __float_as_uint(s_a[(r0 + 8) * 36 + ds + thr]);
                a[mi][2] = __float_as_uint(s_a[r0 * 36 + ds + thr + 4]);
                a[mi][3] = __float_as_uint(s_a[(r0 + 8) * 36 + ds + thr + 4]);
            }
#pragma unroll
            for (int ni = 0; ni < 8; ni++) {
                int f = wf * 64 + ni * 8 + grp;
                uint32_t b0 = __float_as_uint(s_w[(ds + thr) * WSTR + f]);
                uint32_t b1 = __float_as_uint(s_w[(ds + thr + 4) * WSTR + f]);
                mma8(acc[0][ni], a[0], b0, b1);
                mma8(acc[1][ni], a[1], b0, b1);
            }
        }
    }

#pragma unroll
    for (int mi = 0; mi < 2; mi++) {
#pragma unroll
        for (int ci = 0; ci < 4; ci++) {
            int mrow = wl * 32 + mi * 16 + grp + ((ci >= 2) ? 8 : 0);
#pragma unroll
            for (int ni = 0; ni < 8; ni++) {
                int n = wf * 64 + ni * 8 + 2 * thr + (ci & 1);
                float v = acc[mi][ni][ci];
                if (TANH) v = to_tf32(tanhf(v));
                if (TRANSOUT) {
                    int c = n0 + n;
                    if (c < cclamp) out[(size_t)c * LL + m0 + mrow] = v;
                } else {
                    out[(size_t)(m0 + mrow) * ostr + n0 + n] = v;
                }
            }
        }
    }
}

template<int CINP, int WF, bool TANH, bool TRANSOUT>
__global__ void k_mma_nt(const float* __restrict__ A, const float* __restrict__ Bt,
                         float* __restrict__ out, int nstride,
                         size_t a_bstr, size_t o_bstr, int ostr, int cclamp) {
    int b = blockIdx.z;
    mma_nt_body<CINP, WF, TANH, TRANSOUT>(
        A + (size_t)b * a_bstr, Bt, out + (size_t)b * o_bstr,
        nstride, ostr, cclamp);
}

// 3-branch merged variant: z = s*BB + b; Bt selected per branch
struct Ptr3 { const float* p[3]; };

template<int CINP, int WF, bool TANH, bool TRANSOUT>
__global__ void k_mma_nt3(const float* __restrict__ A, Ptr3 bt,
                          float* __restrict__ out, int nstride,
                          size_t a_brstr, size_t a_bstr,
                          size_t o_brstr, size_t o_bstr, int ostr, int cclamp) {
    int z = blockIdx.z;
    int s = z >> 4, b = z & 15;
    mma_nt_body<CINP, WF, TANH, TRANSOUT>(
        A + (size_t)s * a_brstr + (size_t)b * a_bstr, bt.p[s],
        out + (size_t)s * o_brstr + (size_t)b * o_bstr,
        nstride, ostr, cclamp);
}

// ---------------- softmax stats (merged over branches via z) ----------------
__global__ void k_soft(const float* __restrict__ logits, float* __restrict__ rmax,
                       float* __restrict__ rsinv) {
    __shared__ float sred[256];
    int c = blockIdx.x, b = blockIdx.y, s = blockIdx.z, tid = threadIdx.x;
    const float* row = logits + (size_t)s * LOGSZ + ((size_t)b * CC + c) * LL;
    int sidx = s * BB * CC + b * CC + c;
    float m = -1e30f;
    for (int l = tid; l < LL; l += 256) m = fmaxf(m, row[l]);
    sred[tid] = m; __syncthreads();
    for (int st = 128; st > 0; st >>= 1) {
        if (tid < st) sred[tid] = fmaxf(sred[tid], sred[tid + st]);
        __syncthreads();
    }
    m = sred[0]; __syncthreads();
    float sum = 0.f;
    for (int l = tid; l < LL; l += 256) sum += expf(row[l] - m);
    sred[tid] = sum; __syncthreads();
    for (int st = 128; st > 0; st >>= 1) {
        if (tid < st) sred[tid] += sred[tid + st];
        __syncthreads();
    }
    if (tid == 0) { rmax[sidx] = m; rsinv[sidx] = 1.f / sred[0]; }
}

// ---------------- V partials (merged): z = s*BB + b -------------------------
__global__ void k_v(const float* __restrict__ tbase, const float* __restrict__ lgbase,
                    const float* __restrict__ rmax, const float* __restrict__ rsinv,
                    float* __restrict__ vpbase) {
    __shared__ float s_w[25][256];
    int cgrp = blockIdx.x, chunk = blockIdx.y;
    int z = blockIdx.z, s = z >> 4, b = z & 15;
    const float* t  = tbase + (size_t)s * T0SZ;
    const float* lg = lgbase + (size_t)s * LOGSZ;
    float* vpart = vpbase + (size_t)s * VPSZ;
    int tid = threadIdx.x;                 // 128 threads
    int l0 = chunk * 256;
    for (int idx = tid; idx < 25 * 256; idx += 128) {
        int cl = idx >> 8, ll = idx & 255;
        int c = cgrp * 25 + cl;
        int sidx = s * BB * CC + b * CC + c;
        float m = rmax[sidx], si = rsinv[sidx];
        s_w[cl][ll] = expf(lg[((size_t)b * CC + c) * LL + l0 + ll] - m) * si;
    }
    __syncthreads();
    float acc[25];
#pragma unroll
    for (int c = 0; c < 25; c++) acc[c] = 0.f;
    int f = tid;
    for (int ll = 0; ll < 256; ll++) {
        float tv = (f < FF) ? t[((size_t)b * LL + l0 + ll) * FP + f] : 0.f;
#pragma unroll
        for (int c = 0; c < 25; c++) acc[c] += s_w[c][ll] * tv;
    }
    if (f < FF) {
#pragma unroll
        for (int c = 0; c < 25; c++) {
            int cg = cgrp * 25 + c;
            vpart[(((size_t)chunk * BB + b) * CC + cg) * FF + f] = acc[c];
        }
    }
}

// zslot s -> original branch (2-s) for the concat-ordered V region
__global__ void k_vred(const float* __restrict__ vpbase, float* __restrict__ V) {
    size_t idx = (size_t)blockIdx.x * 256 + threadIdx.x;
    if (idx >= 3 * VSZ) return;
    int s = (int)(idx / VSZ);
    size_t rem = idx % VSZ;
    float sum = 0.f;
#pragma unroll
    for (int ch = 0; ch < 16; ch++)
        sum += vpbase[(size_t)s * VPSZ + (size_t)ch * VSZ + rem];
    V[(size_t)(2 - s) * VSZ + rem] = sum;
}

// ---------------- GCN ------------------------------------------------------
__global__ void k_nodes(const int* __restrict__ nodes, const float* __restrict__ emb,
                        float* __restrict__ xn) {
    size_t idx = (size_t)blockIdx.x * 256 + threadIdx.x;
    if (idx >= (size_t)BB * NN * DD) return;
    int d = (int)(idx & (DD - 1));
    size_t row = idx >> 8;
    xn[idx] = to_tf32(emb[(size_t)nodes[row] * DD + d]);
}

__global__ void k_deginit(int* __restrict__ deg) {
    int idx = blockIdx.x * 256 + threadIdx.x;
    if (idx < BB * NN) deg[idx] = 1;   // self loop
}

__global__ void k_degadd(const int* __restrict__ edges, int* __restrict__ deg) {
    int idx = blockIdx.x * 256 + threadIdx.x;
    if (idx >= BB * EE) return;
    int b = idx / EE, e = idx % EE;
    int dst = edges[(b * 2 + 1) * EE + e];
    atomicAdd(&deg[b * NN + dst], 1);
}

__global__ void k_dinv(const int* __restrict__ deg, float* __restrict__ dinv) {
    int idx = blockIdx.x * 256 + threadIdx.x;
    if (idx < BB * NN) dinv[idx] = rsqrtf((float)deg[idx]);
}

__global__ void k_self(const float* __restrict__ xw, const float* __restrict__ dinv,
                       float* __restrict__ out, int rows) {
    size_t idx = (size_t)blockIdx.x * 256 + threadIdx.x;
    if (idx >= (size_t)BB * rows * DD) return;
    int o = (int)(idx & (DD - 1));
    size_t row = idx >> 8;
    int b = (int)(row / rows);
    int n = (int)(row % rows);
    float di = dinv[b * NN + n];
    out[idx] = di * di * xw[((size_t)b * NN + n) * DD + o];
}

__global__ void k_edge(const int* __restrict__ edges, const float* __restrict__ dinv,
                       const float* __restrict__ xw, float* __restrict__ out,
                       int dstmax) {
    int b = blockIdx.y;
    int eloc = threadIdx.x >> 5, lane = threadIdx.x & 31;
    int e = blockIdx.x * 8 + eloc;
    int src = edges[(b * 2) * EE + e];
    int dst = edges[(b * 2 + 1) * EE + e];
    if (dst >= dstmax) return;
    float norm = dinv[b * NN + src] * dinv[b * NN + dst];
    const float* xr = xw + ((size_t)b * NN + src) * DD;
    float* orow = out + ((size_t)b * dstmax + dst) * DD;
#pragma unroll
    for (int j = 0; j < 8; j++) {
        int o = lane + j * 32;
        atomicAdd(&orow[o], norm * xr[o]);
    }
}

__global__ void k_post(float* __restrict__ buf, const float* __restrict__ bias,
                       int rows, int dorelu) {
    size_t idx = (size_t)blockIdx.x * 256 + threadIdx.x;
    if (idx >= (size_t)BB * rows * DD) return;
    int o = (int)(idx & (DD - 1));
    float v = buf[idx] + bias[o];
    if (dorelu) v = fmaxf(v, 0.f);
    buf[idx] = to_tf32(v);
}

// ---------------- final MLP --------------------------------------------------
__global__ void k_final(const float* __restrict__ gout, const float* __restrict__ V,
                        const float* __restrict__ f1T, const float* __restrict__ f1b,
                        const float* __restrict__ f2w, const float* __restrict__ f2b,
                        float* __restrict__ y) {
    __shared__ float s_feat[FEAT];
    __shared__ float s_red[FFNH];
    int c = blockIdx.x, b = blockIdx.y, h = threadIdx.x;   // 128 threads
    for (int idx = h; idx < FEAT; idx += FFNH) {
        float v;
        if (idx < DD) {
            v = gout[((size_t)b * CC + c) * DD + idx];
        } else {
            int br = (idx - DD) / FF;
            int f  = (idx - DD) % FF;
            v = V[(((size_t)br * BB + b) * CC + c) * FF + f];
        }
        s_feat[idx] = v;
    }
    __syncthreads();
    float acc = f1b[h];
    for (int k = 0; k < FEAT; k++) acc += f1T[k * FFNH + h] * s_feat[k];
    float hid = fmaxf(acc, 0.f);
    s_red[h] = f2w[c * FFNH + h] * hid;
    __syncthreads();
    for (int s = 64; s > 0; s >>= 1) {
        if (h < s) s_red[h] += s_red[h + s];
        __syncthreads();
    }
    if (h == 0) y[b * CC + c] = s_red[0] + f2b[c];
}

extern "C" void kernel_launch(void* const* d_in, const int* in_sizes, int n_in,
                              void* d_out, int out_size) {
    const int*   x        = (const int*)d_in[0];
    const int*   nodes    = (const int*)d_in[2];
    const int*   edges    = (const int*)d_in[3];
    const float* word_emb = (const float*)d_in[4];
    const float* ent_emb  = (const float*)d_in[5];
    const float* convw3   = (const float*)d_in[6];
    const float* convb3   = (const float*)d_in[7];
    const float* resw3    = (const float*)d_in[8];
    const float* convw5   = (const float*)d_in[9];
    const float* convb5   = (const float*)d_in[10];
    const float* resw5    = (const float*)d_in[11];
    const float* convw9   = (const float*)d_in[12];
    const float* convb9   = (const float*)d_in[13];
    const float* resw9    = (const float*)d_in[14];
    const float* bn_gamma = (const float*)d_in[15];
    const float* bn_beta  = (const float*)d_in[16];
    const float* attn_w   = (const float*)d_in[17];
    const float* attn_u   = (const float*)d_in[18];
    const float* gc1_w    = (const float*)d_in[19];
    const float* gc1_b    = (const float*)d_in[20];
    const float* gc2_w    = (const float*)d_in[21];
    const float* gc2_b    = (const float*)d_in[22];
    const float* fin1_w   = (const float*)d_in[23];
    const float* fin1_b   = (const float*)d_in[24];
    const float* fin2_w   = (const float*)d_in[25];
    const float* fin2_b   = (const float*)d_in[26];
    float* out = (float*)d_out;

    float* buf; int* deg;
    cudaGetSymbolAddress((void**)&buf, g_buf);
    cudaGetSymbolAddress((void**)&deg, g_deg);

    float* wA = buf + OFF_WA;
    float* wB = buf + OFF_WB;
    // regions indexed by ORIGINAL branch (0=K3,1=K5,2=K9)
    const size_t wA_off[3] = {0, 3 * (size_t)DD * FP, 8 * (size_t)DD * FP};
    const size_t wB_off[6] = {0, 3 * (size_t)FP * FP,
                              6 * (size_t)FP * FP, 11 * (size_t)FP * FP,
                              16 * (size_t)FP * FP, 25 * (size_t)FP * FP};

    PrepPtrs P;
    P.cw0 = convw3; P.cw1 = convw5; P.cw2 = convw9;
    P.rw0 = resw3;  P.rw1 = resw5;  P.rw2 = resw9;
    P.aw = attn_w;  P.au = attn_u;
    P.gc1 = gc1_w;  P.gc2 = gc2_w;  P.f1 = fin1_w;
    P.wA0 = wA + wA_off[0]; P.wA1 = wA + wA_off[1]; P.wA2 = wA + wA_off[2];
    P.wB0 = wB + wB_off[0]; P.wB1 = wB + wB_off[1]; P.wB2 = wB + wB_off[2];
    P.wB3 = wB + wB_off[3]; P.wB4 = wB + wB_off[4]; P.wB5 = wB + wB_off[5];
    P.awp = buf + OFF_AWP; P.aup = buf + OFF_AUP;
    P.gwt = buf + OFF_GWT; P.f1T = buf + OFF_F1T;

    // zslot s: 0->K9 (orig 2), 1->K5 (orig 1), 2->K3 (orig 0)
    const int obr[3] = {2, 1, 0};
    const float* cbs[3]  = {convb9, convb5, convb3};
    float* t0s[3]; float* t1s[3];
    for (int s = 0; s < 3; s++) {
        t0s[s] = buf + OFF_T0 + (size_t)s * T0SZ;
        t1s[s] = buf + OFF_T1 + (size_t)s * T0SZ;
    }

    cudaFuncSetAttribute(k_conv_multi<DD>, cudaFuncAttributeMaxDynamicSharedMemorySize,
                         conv_multi_smem());
    cudaFuncSetAttribute(k_conv_multi<FP>, cudaFuncAttributeMaxDynamicSharedMemorySize,
                         conv_multi_smem());

    // launch 1: embed; 2: preps; 3: deg init; 4: merged conv phase1 (profiled)
    k_embed<<<(int)(((size_t)BB * LL * DD + 255) / 256), 256>>>(x, word_emb, buf + OFF_H);
    k_prep_all<<<dim3(1152, 18), 256>>>(P);
    k_deginit<<<(BB * NN + 255) / 256, 256>>>(deg);

    dim3 cgrid(LL / 128, BB, 3);

    ConvMulti A1;
    for (int s = 0; s < 3; s++) {
        int ob = obr[s];
        A1.in[s] = buf + OFF_H;
        A1.wT[s] = wA + wA_off[ob];
        A1.cb[s] = cbs[s];
        A1.gma[s] = bn_gamma + (size_t)ob * 3 * FF;
        A1.bta[s] = bn_beta + (size_t)ob * 3 * FF;
        A1.resid[s] = nullptr;
        A1.out[s] = t0s[s];
    }
    A1.mode = 0;
    k_conv_multi<DD><<<cgrid, 256, conv_multi_smem()>>>(A1);

    ConvMulti A2;
    for (int s = 0; s < 3; s++) {
        int ob = obr[s];
        A2.in[s] = t0s[s];
        A2.wT[s] = wB + wB_off[ob * 2 + 0];
        A2.cb[s] = nullptr;
        A2.gma[s] = bn_gamma + (size_t)ob * 3 * FF + FF;
        A2.bta[s] = bn_beta + (size_t)ob * 3 * FF + FF;
        A2.resid[s] = t0s[s];
        A2.out[s] = t1s[s];
    }
    A2.mode = 1;
    k_conv_multi<FP><<<cgrid, 256, conv_multi_smem()>>>(A2);

    ConvMulti A3;
    for (int s = 0; s < 3; s++) {
        int ob = obr[s];
        A3.in[s] = t1s[s];
        A3.wT[s] = wB + wB_off[ob * 2 + 1];
        A3.cb[s] = nullptr;
        A3.gma[s] = bn_gamma + (size_t)ob * 3 * FF + 2 * FF;
        A3.bta[s] = bn_beta + (size_t)ob * 3 * FF + 2 * FF;
        A3.resid[s] = t1s[s];
        A3.out[s] = t0s[s];
    }
    A3.mode = 1;
    k_conv_multi<FP><<<cgrid, 256, conv_multi_smem()>>>(A3);

    // merged attention GEMMs
    Ptr3 btZ, btL;
    for (int s = 0; s < 3; s++) {
        btZ.p[s] = buf + OFF_AWP + (size_t)obr[s] * FP * AA;
        btL.p[s] = buf + OFF_AUP + (size_t)obr[s] * AA * 64;
    }
    // Z[s][b][l][a] = tanh(t0 . aw^T)
    k_mma_nt3<FP, 2, true, false><<<dim3(LL / 128, AA / 128, 48), 256>>>(
        buf + OFF_T0, btZ, buf + OFF_Z, AA,
        T0SZ, (size_t)LL * FP, ZSZ, (size_t)LL * AA, AA, 0);
    // logits[s][b][c][l] = Z . au^T (transposed store)
    k_mma_nt3<AA, 1, false, true><<<dim3(LL / 128, 1, 48), 128>>>(
        buf + OFF_Z, btL, buf + OFF_LOG, 64,
        ZSZ, (size_t)LL * AA, LOGSZ, (size_t)CC * LL, 0, CC);

    k_soft<<<dim3(CC, BB, 3), 256>>>(buf + OFF_LOG, buf + OFF_RMAX, buf + OFF_RSINV);
    k_v<<<dim3(2, 16, 48), 128>>>(buf + OFF_T0, buf + OFF_LOG,
                                  buf + OFF_RMAX, buf + OFF_RSINV, buf + OFF_VPART);
    k_vred<<<(int)((3 * VSZ + 255) / 256), 256>>>(buf + OFF_VPART, buf + OFF_V);

    // GCN
    float* xn   = buf + OFF_XN;
    float* xw   = buf + OFF_XW;
    float* g1   = buf + OFF_G1;
    float* gout = buf + OFF_GOUT;
    float* dinv = buf + OFF_DINV;
    float* gwt1 = buf + OFF_GWT;
    float* gwt2 = buf + OFF_GWT + (size_t)DD * DD;
    k_nodes<<<(int)(((size_t)BB * NN * DD + 255) / 256), 256>>>(nodes, ent_emb, xn);
    k_degadd<<<(BB * EE + 255) / 256, 256>>>(edges, deg);
    k_dinv<<<(BB * NN + 255) / 256, 256>>>(deg, dinv);

    k_mma_nt<DD, 2, false, false><<<dim3(NN / 128, DD / 128, BB), 256>>>(
        xn, gwt1, xw, DD, (size_t)NN * DD, (size_t)NN * DD, DD, 0);
    k_self<<<(int)(((size_t)BB * NN * DD + 255) / 256), 256>>>(xw, dinv, g1, NN);
    k_edge<<<dim3(EE / 8, BB), 256>>>(edges, dinv, xw, g1, NN);
    k_post<<<(int)(((size_t)BB * NN * DD + 255) / 256), 256>>>(g1, gc1_b, NN, 1);

    k_mma_nt<DD, 2, false, false><<<dim3(NN / 128, DD / 128, BB), 256>>>(
        g1, gwt2, xw, DD, (size_t)NN * DD, (size_t)NN * DD, DD, 0);
    k_self<<<(int)(((size_t)BB * CC * DD + 255) / 256), 256>>>(xw, dinv, gout, CC);
    k_edge<<<dim3(EE / 8, BB), 256>>>(edges, dinv, xw, gout, CC);
    k_post<<<(int)(((size_t)BB * CC * DD + 255) / 256), 256>>>(gout, gc2_b, CC, 0);

    // final MLP
    k_final<<<dim3(CC, BB), FFNH>>>(gout, buf + OFF_V, buf + OFF_F1T,
                                    fin1_b, fin2_w, fin2_b, out);
}

// round 16
// speedup vs baseline: 1.4488x; 1.0309x over previous
#include <cuda_runtime.h>
#include <math.h>
#include <stdint.h>

#define BB   16
#define LL   4096
#define DD   256
#define CC   50
#define NN   512
#define EE   8192
#define FF   100
#define FP   128
#define AA   256
#define FFNH 128
#define FEAT 556   /* 256 + 3*100 */

static constexpr size_t T0SZ  = (size_t)BB*LL*FP;
static constexpr size_t ZSZ   = (size_t)BB*LL*AA;
static constexpr size_t LOGSZ = (size_t)BB*CC*LL;
static constexpr size_t VPSZ  = (size_t)16*BB*CC*FF;
static constexpr size_t VSZ   = (size_t)BB*CC*FF;

// ---------------- one big static scratch buffer (no allocations) ------------
static constexpr size_t OFF_H     = 0;
static constexpr size_t OFF_T0    = OFF_H     + (size_t)BB*LL*DD;
static constexpr size_t OFF_T1    = OFF_T0    + 3*T0SZ;
static constexpr size_t OFF_Z     = OFF_T1    + 3*T0SZ;
static constexpr size_t OFF_LOG   = OFF_Z     + 3*ZSZ;
static constexpr size_t OFF_RMAX  = OFF_LOG   + 3*LOGSZ;
static constexpr size_t OFF_RSINV = OFF_RMAX  + (size_t)3*BB*CC;
static constexpr size_t OFF_VPART = OFF_RSINV + (size_t)3*BB*CC;
static constexpr size_t OFF_V     = OFF_VPART + 3*VPSZ;
static constexpr size_t OFF_WA    = OFF_V     + 3*VSZ;
static constexpr size_t OFF_WB    = OFF_WA    + (size_t)3*9*DD*FP;
static constexpr size_t OFF_AWP   = OFF_WB    + (size_t)6*9*FP*FP;
static constexpr size_t OFF_AUP   = OFF_AWP   + (size_t)3*FP*AA;
static constexpr size_t OFF_GWT   = OFF_AUP   + (size_t)3*AA*64;
static constexpr size_t OFF_XN    = OFF_GWT   + (size_t)2*DD*DD;
static constexpr size_t OFF_XW    = OFF_XN    + (size_t)BB*NN*DD;
static constexpr size_t OFF_G1    = OFF_XW    + (size_t)BB*NN*DD;
static constexpr size_t OFF_GOUT  = OFF_G1    + (size_t)BB*NN*DD;
static constexpr size_t OFF_F1T   = OFF_GOUT  + (size_t)BB*CC*DD;
static constexpr size_t OFF_DINV  = OFF_F1T   + (size_t)FEAT*FFNH;
static constexpr size_t BUF_TOTAL = OFF_DINV  + (size_t)BB*NN;

__device__ float g_buf[BUF_TOTAL];
__device__ int   g_deg[BB*NN];

// ---------------- helpers ----------------------------------------------------
__device__ __forceinline__ float to_tf32(float x) {
    float r;
    asm("cvt.rna.tf32.f32 %0, %1;" : "=f"(r) : "f"(x));
    return r;
}

__device__ __forceinline__ void mma8(float d[4], const uint32_t a[4],
                                     uint32_t b0, uint32_t b1) {
    asm volatile(
        "mma.sync.aligned.m16n8k8.row.col.f32.tf32.tf32.f32 "
        "{%0,%1,%2,%3}, {%4,%5,%6,%7}, {%8,%9}, {%0,%1,%2,%3};\n"
        : "+f"(d[0]), "+f"(d[1]), "+f"(d[2]), "+f"(d[3])
        : "r"(a[0]), "r"(a[1]), "r"(a[2]), "r"(a[3]), "r"(b0), "r"(b1));
}

__device__ __forceinline__ void cp16(float* dst_smem, const float* src, bool pred) {
    uint32_t d = (uint32_t)__cvta_generic_to_shared(dst_smem);
    int sz = pred ? 16 : 0;
    asm volatile("cp.async.cg.shared.global [%0], [%1], 16, %2;\n"
                 :: "r"(d), "l"(src), "r"(sz));
}
__device__ __forceinline__ void cp_commit() {
    asm volatile("cp.async.commit_group;\n");
}
__device__ __forceinline__ void cp_wait0() {
    asm volatile("cp.async.wait_group 0;\n");
}
__device__ __forceinline__ void cp_wait1() {
    asm volatile("cp.async.wait_group 1;\n");
}

// ---------------- embedding gather  h[b][l][d] (tf32-rounded) ----------------
__global__ void k_embed(const int* __restrict__ x, const float* __restrict__ emb,
                        float* __restrict__ h) {
    size_t idx = (size_t)blockIdx.x * 256 + threadIdx.x;
    if (idx >= (size_t)BB*LL*DD) return;
    int d = (int)(idx & (DD - 1));
    size_t row = idx >> 8;
    h[idx] = to_tf32(emb[(size_t)x[row] * DD + d]);
}

// ---------------- merged prep kernel (18 segments) ---------------------------
struct PrepPtrs {
    const float *cw0, *cw1, *cw2;     // convw3/5/9 [F][DD][K]
    const float *rw0, *rw1, *rw2;     // resw3/5/9  [2][F][FF][K]
    const float *aw, *au, *gc1, *gc2, *f1;
    float *wA0, *wA1, *wA2;
    float *wB0, *wB1, *wB2, *wB3, *wB4, *wB5;
    float *awp, *aup, *gwt, *f1T;
};

__global__ void k_prep_all(PrepPtrs P) {
    int seg = blockIdx.y;
    int idx0 = blockIdx.x * 256 + threadIdx.x;
    int stride = gridDim.x * 256;
    if (seg < 3) {                       // wA: [K][DD][FP], CIN=DD
        int K = (seg == 0) ? 3 : (seg == 1) ? 5 : 9;
        const float* src = (seg == 0) ? P.cw0 : (seg == 1) ? P.cw1 : P.cw2;
        float* dst = (seg == 0) ? P.wA0 : (seg == 1) ? P.wA1 : P.wA2;
        int tot = K * DD * FP;
        for (int idx = idx0; idx < tot; idx += stride) {
            int f = idx & 127;
            int rem = idx >> 7;
            int d = rem % DD;
            int k = rem / DD;
            dst[idx] = (f < FF) ? to_tf32(src[(f * DD + d) * K + k]) : 0.f;
        }
    } else if (seg < 9) {                // wB: [K][FP][FP], CIN=FF
        int inst = seg - 3, br = inst >> 1, which = inst & 1;
        int K = (br == 0) ? 3 : (br == 1) ? 5 : 9;
        const float* base = (br == 0) ? P.rw0 : (br == 1) ? P.rw1 : P.rw2;
        const float* src = base + (size_t)which * FF * FF * K;
        float* dst = (inst == 0) ? P.wB0 : (inst == 1) ? P.wB1 : (inst == 2) ? P.wB2 :
                     (inst == 3) ? P.wB3 : (inst == 4) ? P.wB4 : P.wB5;
        int tot = K * FP * FP;
        for (int idx = idx0; idx < tot; idx += stride) {
            int f = idx & 127;
            int rem = idx >> 7;
            int d = rem % FP;
            int k = rem / FP;
            dst[idx] = (f < FF && d < FF) ? to_tf32(src[(f * FF + d) * K + k]) : 0.f;
        }
    } else if (seg < 12) {               // awp: Bt[k(FP)][a(AA)]
        int br = seg - 9;
        const float* src = P.aw + (size_t)br * AA * FF;
        float* dst = P.awp + (size_t)br * FP * AA;
        int tot = FP * AA;
        for (int idx = idx0; idx < tot; idx += stride) {
            int k = idx >> 8, n = idx & (AA - 1);
            dst[idx] = (k < FF) ? to_tf32(src[n * FF + k]) : 0.f;
        }
    } else if (seg < 15) {               // aup: Bt[k(AA)][c(64)]
        int br = seg - 12;
        const float* src = P.au + (size_t)br * CC * AA;
        float* dst = P.aup + (size_t)br * AA * 64;
        int tot = AA * 64;
        for (int idx = idx0; idx < tot; idx += stride) {
            int k = idx >> 6, n = idx & 63;
            dst[idx] = (n < CC) ? to_tf32(src[n * AA + k]) : 0.f;
        }
    } else if (seg < 17) {               // GCN weight transposes
        const float* src = (seg == 15) ? P.gc1 : P.gc2;
        float* dst = P.gwt + (size_t)(seg - 15) * DD * DD;
        int tot = DD * DD;
        for (int idx = idx0; idx < tot; idx += stride) {
            int k = idx >> 8, n = idx & (DD - 1);
            dst[idx] = to_tf32(src[n * DD + k]);
        }
    } else {                             // f1T
        int tot = FEAT * FFNH;
        for (int idx = idx0; idx < tot; idx += stride) {
            int h = idx & (FFNH - 1), k = idx >> 7;
            P.f1T[idx] = P.f1[h * FEAT + k];
        }
    }
}

// ---------------- conv body: double-buffered input AND weights ---------------
template<int K, int CINP>
__device__ __forceinline__ void conv_body(
    const float* __restrict__ in, const float* __restrict__ wT,
    const float* __restrict__ cb, const float* __restrict__ gamma,
    const float* __restrict__ beta, const float* __restrict__ resid,
    float* __restrict__ out, int mode, float* smem) {
    constexpr int LT = 128;
    constexpr int PAD = K / 2;
    constexpr int ROWS = LT + K - 1;
    constexpr int ISTR = 36;
    constexpr int ITILE = ROWS * ISTR;
    constexpr int WSTR = 136;
    constexpr int WTILE = 32 * WSTR;
    constexpr int NC = CINP / 32;
    float* s_in = smem;                 // 2 * ITILE
    float* s_w  = smem + 2 * ITILE;     // 2 * WTILE

    int b = blockIdx.y, l0 = blockIdx.x * LT, tid = threadIdx.x;
    int wid = tid >> 5, lane = tid & 31;
    int wl = wid >> 1, wf = wid & 1;
    int grp = lane >> 2, thr = lane & 3;

    float acc[2][8][4];
#pragma unroll
    for (int mi = 0; mi < 2; mi++)
#pragma unroll
        for (int ni = 0; ni < 8; ni++)
#pragma unroll
            for (int ci = 0; ci < 4; ci++) acc[mi][ni][ci] = 0.f;

    const float* inb = in + (size_t)b * LL * CINP;

    auto fill_input = [&](int c, int bufi) {
        float* dst = s_in + bufi * ITILE;
        for (int t = tid; t < ROWS * 8; t += 256) {
            int row = t >> 3, seg = t & 7;
            int gl = l0 - PAD + row;
            cp16(&dst[row * ISTR + seg * 4],
                 inb + (size_t)gl * CINP + c * 32 + seg * 4,
                 (gl >= 0 && gl < LL));
        }
    };
    auto fill_w = [&](int kk, int cc, int bufw) {
        const float* wk = wT + ((size_t)kk * CINP + cc * 32) * FP;
        float* dst = s_w + bufw * WTILE;
        for (int t = tid; t < 32 * 32; t += 256) {
            int dd = t >> 5, seg = t & 31;
            cp16(&dst[dd * WSTR + seg * 4], wk + dd * FP + seg * 4, true);
        }
    };

    fill_input(0, 0);
    fill_w(0, 0, 0);
    cp_commit();
    cp_wait0();
    __syncthreads();

    for (int c = 0; c < NC; c++) {
        int cur = c & 1;
        const float* sin = s_in + cur * ITILE;
#pragma unroll
        for (int k = 0; k < K; k++) {
            int g = c * K + k;
            bool haveW = (g + 1 < NC * K);
            if (haveW) {
                int nk = (k + 1 < K) ? k + 1 : 0;
                int ncd = (k + 1 < K) ? c : c + 1;
                fill_w(nk, ncd, (g + 1) & 1);
                cp_commit();
            }
            bool haveI = (k == 0 && c + 1 < NC);
            if (haveI) {
                fill_input(c + 1, 1 - cur);
                cp_commit();
            }
            const float* curw = s_w + (g & 1) * WTILE;
#pragma unroll
            for (int ds = 0; ds < 32; ds += 8) {
                uint32_t a[2][4];
#pragma unroll
                for (int mi = 0; mi < 2; mi++) {
                    int r0 = wl * 32 + mi * 16 + grp + k;
                    a[mi][0] = __float_as_uint(sin[r0 * ISTR + ds + thr]);
                    a[mi][1] = __float_as_uint(sin[(r0 + 8) * ISTR + ds + thr]);
                    a[mi][2] = __float_as_uint(sin[r0 * ISTR + ds + thr + 4]);
                    a[mi][3] = __float_as_uint(sin[(r0 + 8) * ISTR + ds + thr + 4]);
                }
#pragma unroll
                for (int ni = 0; ni < 8; ni++) {
                    int f = wf * 64 + ni * 8 + grp;
                    uint32_t b0 = __float_as_uint(curw[(ds + thr) * WSTR + f]);
                    uint32_t b1 = __float_as_uint(curw[(ds + thr + 4) * WSTR + f]);
                    mma8(acc[0][ni], a[0], b0, b1);
                    mma8(acc[1][ni], a[1], b0, b1);
                }
            }
            // FIFO: weight group committed before input group, so wait_group 1
            // completes weights while the input prefetch may linger one tap.
            if (haveI && haveW) cp_wait1();
            else cp_wait0();
            __syncthreads();
        }
    }

    const float BNI = rsqrtf(1.f + 1e-5f);
#pragma unroll
    for (int mi = 0; mi < 2; mi++) {
#pragma unroll
        for (int ci = 0; ci < 4; ci++) {
            int l = l0 + wl * 32 + mi * 16 + grp + ((ci >= 2) ? 8 : 0);
            size_t base = ((size_t)b * LL + l) * FP;
#pragma unroll
            for (int ni = 0; ni < 8; ni++) {
                int f = wf * 64 + ni * 8 + 2 * thr + (ci & 1);
                float v = acc[mi][ni][ci];
                float o;
                if (f < FF) {
                    float sc = gamma[f] * BNI, bt = beta[f];
                    if (mode == 0) o = tanhf(v + cb[f]) * sc + bt;
                    else           o = tanhf(v * sc + bt + resid[base + f]);
                    o = to_tf32(o);
                } else {
                    o = 0.f;
                }
                out[base + f] = o;
            }
        }
    }
}

// Merged 3-branch conv: z=0 -> K9, z=1 -> K5, z=2 -> K3 (heavy first)
struct ConvMulti {
    const float* in[3];
    const float* wT[3];
    const float* cb[3];
    const float* gma[3];
    const float* bta[3];
    const float* resid[3];
    float* out[3];
    int mode;
};

template<int CINP>
__global__ void __launch_bounds__(256, 2) k_conv_multi(ConvMulti A) {
    extern __shared__ float smem[];
    int s = blockIdx.z;
    if (s == 0)
        conv_body<9, CINP>(A.in[0], A.wT[0], A.cb[0], A.gma[0], A.bta[0],
                           A.resid[0], A.out[0], A.mode, smem);
    else if (s == 1)
        conv_body<5, CINP>(A.in[1], A.wT[1], A.cb[1], A.gma[1], A.bta[1],
                           A.resid[1], A.out[1], A.mode, smem);
    else
        conv_body<3, CINP>(A.in[2], A.wT[2], A.cb[2], A.gma[2], A.bta[2],
                           A.resid[2], A.out[2], A.mode, smem);
}

static constexpr int conv_multi_smem() {
    return (2 * (128 + 9 - 1) * 36 + 2 * 32 * 136) * 4;   // max over K
}

// ---------------- generic tf32 NT GEMM bodies -------------------------------
template<int CINP, int WF, bool TANH, bool TRANSOUT>
__device__ __forceinline__ void mma_nt_body(
    const float* __restrict__ A, const float* __restrict__ Bt,
    float* __restrict__ out, int nstride, int ostr, int cclamp) {
    constexpr int NT = WF * 128;
    constexpr int WIDTH = WF * 64;
    constexpr int WSTR = WIDTH + 8;
    __shared__ float s_a[128 * 36];
    __shared__ float s_w[32 * WSTR];
    int m0 = blockIdx.x * 128;
    int n0 = blockIdx.y * WIDTH;
    int tid = threadIdx.x;
    int wid = tid >> 5, lane = tid & 31;
    int wl = wid / WF, wf = wid % WF;
    int grp = lane >> 2, thr = lane & 3;

    float acc[2][8][4];
#pragma unroll
    for (int mi = 0; mi < 2; mi++)
#pragma unroll
        for (int ni = 0; ni < 8; ni++)
#pragma unroll
            for (int ci = 0; ci < 4; ci++) acc[mi][ni][ci] = 0.f;

    for (int k0 = 0; k0 < CINP; k0 += 32) {
        __syncthreads();
        for (int t = tid; t < 128 * 8; t += NT) {
            int row = t >> 3, seg = t & 7;
            cp16(&s_a[row * 36 + seg * 4],
                 A + (size_t)(m0 + row) * CINP + k0 + seg * 4, true);
        }
        for (int t = tid; t < 32 * (WIDTH / 4); t += NT) {
            int dd = t / (WIDTH / 4), seg = t % (WIDTH / 4);
            cp16(&s_w[dd * WSTR + seg * 4],
                 Bt + (size_t)(k0 + dd) * nstride + n0 + seg * 4, true);
        }
        cp_commit();
        cp_wait0();
        __syncthreads();
#pragma unroll
        for (int ds = 0; ds < 32; ds += 8) {
            uint32_t a[2][4];
#pragma unroll
            for (int mi = 0; mi < 2; mi++) {
                int r0 = wl * 32 + mi * 16 + grp;
                a[mi][0] = __float_as_uint(s_a[r0 * 36 + ds + thr]);
                a[mi][1] = __float_as_uint(s_a[(r0 + 8) * 36 + ds + thr]);
                a[mi][2] = __float_as_uint(s_a[r0 * 36 + ds + thr + 4]);
                a[mi][3] = __float_as_uint(s_a[(r0 + 8) * 36 + ds + thr + 4]);
            }
#pragma unroll
            for (int ni = 0; ni < 8; ni++) {
                int f = wf * 64 + ni * 8 + grp;
                uint32_t b0 = __float_as_uint(s_w[(ds + thr) * WSTR + f]);
                uint32_t b1 = __float_as_uint(s_w[(ds + thr + 4) * WSTR + f]);
                mma8(acc[0][ni], a[0], b0, b1);
                mma8(acc[1][ni], a[1], b0, b1);
            }
        }
    }

#pragma unroll
    for (int mi = 0; mi < 2; mi++) {
#pragma unroll
        for (int ci = 0; ci < 4; ci++) {
            int mrow = wl * 32 + mi * 16 + grp + ((ci >= 2) ? 8 : 0);
#pragma unroll
            for (int ni = 0; ni < 8; ni++) {
                int n = wf * 64 + ni * 8 + 2 * thr + (ci & 1);
                float v = acc[mi][ni][ci];
                if (TANH) v = to_tf32(tanhf(v));
                if (TRANSOUT) {
                    int c = n0 + n;
                    if (c < cclamp) out[(size_t)c * LL + m0 + mrow] = v;
                } else {
                    out[(size_t)(m0 + mrow) * ostr + n0 + n] = v;
                }
            }
        }
    }
}

template<int CINP, int WF, bool TANH, bool TRANSOUT>
__global__ void k_mma_nt(const float* __restrict__ A, const float* __restrict__ Bt,
                         float* __restrict__ out, int nstride,
                         size_t a_bstr, size_t o_bstr, int ostr, int cclamp) {
    int b = blockIdx.z;
    mma_nt_body<CINP, WF, TANH, TRANSOUT>(
        A + (size_t)b * a_bstr, Bt, out + (size_t)b * o_bstr,
        nstride, ostr, cclamp);
}

// 3-branch merged variant: z = s*BB + b; Bt selected per branch
struct Ptr3 { const float* p[3]; };

template<int CINP, int WF, bool TANH, bool TRANSOUT>
__global__ void k_mma_nt3(const float* __restrict__ A, Ptr3 bt,
                          float* __restrict__ out, int nstride,
                          size_t a_brstr, size_t a_bstr,
                          size_t o_brstr, size_t o_bstr, int ostr, int cclamp) {
    int z = blockIdx.z;
    int s = z >> 4, b = z & 15;
    mma_nt_body<CINP, WF, TANH, TRANSOUT>(
        A + (size_t)s * a_brstr + (size_t)b * a_bstr, bt.p[s],
        out + (size_t)s * o_brstr + (size_t)b * o_bstr,
        nstride, ostr, cclamp);
}

// ---------------- softmax stats (merged over branches via z) ----------------
__global__ void k_soft(const float* __restrict__ logits, float* __restrict__ rmax,
                       float* __restrict__ rsinv) {
    __shared__ float sred[256];
    int c = blockIdx.x, b = blockIdx.y, s = blockIdx.z, tid = threadIdx.x;
    const float* row = logits + (size_t)s * LOGSZ + ((size_t)b * CC + c) * LL;
    int sidx = s * BB * CC + b * CC + c;
    float m = -1e30f;
    for (int l = tid; l < LL; l += 256) m = fmaxf(m, row[l]);
    sred[tid] = m; __syncthreads();
    for (int st = 128; st > 0; st >>= 1) {
        if (tid < st) sred[tid] = fmaxf(sred[tid], sred[tid + st]);
        __syncthreads();
    }
    m = sred[0]; __syncthreads();
    float sum = 0.f;
    for (int l = tid; l < LL; l += 256) sum += expf(row[l] - m);
    sred[tid] = sum; __syncthreads();
    for (int st = 128; st > 0; st >>= 1) {
        if (tid < st) sred[tid] += sred[tid + st];
        __syncthreads();
    }
    if (tid == 0) { rmax[sidx] = m; rsinv[sidx] = 1.f / sred[0]; }
}

// ---------------- V partials (merged, float4 weights): z = s*BB + b ---------
__global__ void k_v(const float* __restrict__ tbase, const float* __restrict__ lgbase,
                    const float* __restrict__ rmax, const float* __restrict__ rsinv,
                    float* __restrict__ vpbase) {
    __shared__ float4 s_w4[25][64];
    float* s_wf = reinterpret_cast<float*>(s_w4);
    int cgrp = blockIdx.x, chunk = blockIdx.y;
    int z = blockIdx.z, s = z >> 4, b = z & 15;
    const float* t  = tbase + (size_t)s * T0SZ;
    const float* lg = lgbase + (size_t)s * LOGSZ;
    float* vpart = vpbase + (size_t)s * VPSZ;
    int tid = threadIdx.x;                 // 128 threads
    int l0 = chunk * 256;
    for (int idx = tid; idx < 25 * 256; idx += 128) {
        int cl = idx >> 8, ll = idx & 255;
        int c = cgrp * 25 + cl;
        int sidx = s * BB * CC + b * CC + c;
        float m = rmax[sidx], si = rsinv[sidx];
        s_wf[cl * 256 + ll] = expf(lg[((size_t)b * CC + c) * LL + l0 + ll] - m) * si;
    }
    __syncthreads();
    float acc[25];
#pragma unroll
    for (int c = 0; c < 25; c++) acc[c] = 0.f;
    int f = tid;
    bool valid = (f < FF);
    for (int ll4 = 0; ll4 < 64; ll4++) {
        float tv0 = valid ? t[((size_t)b * LL + l0 + ll4 * 4 + 0) * FP + f] : 0.f;
        float tv1 = valid ? t[((size_t)b * LL + l0 + ll4 * 4 + 1) * FP + f] : 0.f;
        float tv2 = valid ? t[((size_t)b * LL + l0 + ll4 * 4 + 2) * FP + f] : 0.f;
        float tv3 = valid ? t[((size_t)b * LL + l0 + ll4 * 4 + 3) * FP + f] : 0.f;
#pragma unroll
        for (int c = 0; c < 25; c++) {
            float4 wv = s_w4[c][ll4];
            acc[c] += wv.x * tv0 + wv.y * tv1 + wv.z * tv2 + wv.w * tv3;
        }
    }
    if (valid) {
#pragma unroll
        for (int c = 0; c < 25; c++) {
            int cg = cgrp * 25 + c;
            vpart[(((size_t)chunk * BB + b) * CC + cg) * FF + f] = acc[c];
        }
    }
}

// zslot s -> original branch (2-s) for the concat-ordered V region
__global__ void k_vred(const float* __restrict__ vpbase, float* __restrict__ V) {
    size_t idx = (size_t)blockIdx.x * 256 + threadIdx.x;
    if (idx >= 3 * VSZ) return;
    int s = (int)(idx / VSZ);
    size_t rem = idx % VSZ;
    float sum = 0.f;
#pragma unroll
    for (int ch = 0; ch < 16; ch++)
        sum += vpbase[(size_t)s * VPSZ + (size_t)ch * VSZ + rem];
    V[(size_t)(2 - s) * VSZ + rem] = sum;
}

// ---------------- GCN ------------------------------------------------------
__global__ void k_nodes(const int* __restrict__ nodes, const float* __restrict__ emb,
                        float* __restrict__ xn) {
    size_t idx = (size_t)blockIdx.x * 256 + threadIdx.x;
    if (idx >= (size_t)BB * NN * DD) return;
    int d = (int)(idx & (DD - 1));
    size_t row = idx >> 8;
    xn[idx] = to_tf32(emb[(size_t)nodes[row] * DD + d]);
}

__global__ void k_deginit(int* __restrict__ deg) {
    int idx = blockIdx.x * 256 + threadIdx.x;
    if (idx < BB * NN) deg[idx] = 1;   // self loop
}

__global__ void k_degadd(const int* __restrict__ edges, int* __restrict__ deg) {
    int idx = blockIdx.x * 256 + threadIdx.x;
    if (idx >= BB * EE) return;
    int b = idx / EE, e = idx % EE;
    int dst = edges[(b * 2 + 1) * EE + e];
    atomicAdd(&deg[b * NN + dst], 1);
}

__global__ void k_dinv(const int* __restrict__ deg, float* __restrict__ dinv) {
    int idx = blockIdx.x * 256 + threadIdx.x;
    if (idx < BB * NN) dinv[idx] = rsqrtf((float)deg[idx]);
}

__global__ void k_self(const float* __restrict__ xw, const float* __restrict__ dinv,
                       float* __restrict__ out, int rows) {
    size_t idx = (size_t)blockIdx.x * 256 + threadIdx.x;
    if (idx >= (size_t)BB * rows * DD) return;
    int o = (int)(idx & (DD - 1));
    size_t row = idx >> 8;
    int b = (int)(row / rows);
    int n = (int)(row % rows);
    float di = dinv[b * NN + n];
    out[idx] = di * di * xw[((size_t)b * NN + n) * DD + o];
}

__global__ void k_edge(const int* __restrict__ edges, const float* __restrict__ dinv,
                       const float* __restrict__ xw, float* __restrict__ out,
                       int dstmax) {
    int b = blockIdx.y;
    int eloc = threadIdx.x >> 5, lane = threadIdx.x & 31;
    int e = blockIdx.x * 8 + eloc;
    int src = edges[(b * 2) * EE + e];
    int dst = edges[(b * 2 + 1) * EE + e];
    if (dst >= dstmax) return;
    float norm = dinv[b * NN + src] * dinv[b * NN + dst];
    const float* xr = xw + ((size_t)b * NN + src) * DD;
    float* orow = out + ((size_t)b * dstmax + dst) * DD;
#pragma unroll
    for (int j = 0; j < 8; j++) {
        int o = lane + j * 32;
        atomicAdd(&orow[o], norm * xr[o]);
    }
}

__global__ void k_post(float* __restrict__ buf, const float* __restrict__ bias,
                       int rows, int dorelu) {
    size_t idx = (size_t)blockIdx.x * 256 + threadIdx.x;
    if (idx >= (size_t)BB * rows * DD) return;
    int o = (int)(idx & (DD - 1));
    float v = buf[idx] + bias[o];
    if (dorelu) v = fmaxf(v, 0.f);
    buf[idx] = to_tf32(v);
}

// ---------------- final MLP --------------------------------------------------
__global__ void k_final(const float* __restrict__ gout, const float* __restrict__ V,
                        const float* __restrict__ f1T, const float* __restrict__ f1b,
                        const float* __restrict__ f2w, const float* __restrict__ f2b,
                        float* __restrict__ y) {
    __shared__ float s_feat[FEAT];
    __shared__ float s_red[FFNH];
    int c = blockIdx.x, b = blockIdx.y, h = threadIdx.x;   // 128 threads
    for (int idx = h; idx < FEAT; idx += FFNH) {
        float v;
        if (idx < DD) {
            v = gout[((size_t)b * CC + c) * DD + idx];
        } else {
            int br = (idx - DD) / FF;
            int f  = (idx - DD) % FF;
            v = V[(((size_t)br * BB + b) * CC + c) * FF + f];
        }
        s_feat[idx] = v;
    }
    __syncthreads();
    float acc = f1b[h];
    for (int k = 0; k < FEAT; k++) acc += f1T[k * FFNH + h] * s_feat[k];
    float hid = fmaxf(acc, 0.f);
    s_red[h] = f2w[c * FFNH + h] * hid;
    __syncthreads();
    for (int s = 64; s > 0; s >>= 1) {
        if (h < s) s_red[h] += s_red[h + s];
        __syncthreads();
    }
    if (h == 0) y[b * CC + c] = s_red[0] + f2b[c];
}

extern "C" void kernel_launch(void* const* d_in, const int* in_sizes, int n_in,
                              void* d_out, int out_size) {
    const int*   x        = (const int*)d_in[0];
    const int*   nodes    = (const int*)d_in[2];
    const int*   edges    = (const int*)d_in[3];
    const float* word_emb = (const float*)d_in[4];
    const float* ent_emb  = (const float*)d_in[5];
    const float* convw3   = (const float*)d_in[6];
    const float* convb3   = (const float*)d_in[7];
    const float* resw3    = (const float*)d_in[8];
    const float* convw5   = (const float*)d_in[9];
    const float* convb5   = (const float*)d_in[10];
    const float* resw5    = (const float*)d_in[11];
    const float* convw9   = (const float*)d_in[12];
    const float* convb9   = (const float*)d_in[13];
    const float* resw9    = (const float*)d_in[14];
    const float* bn_gamma = (const float*)d_in[15];
    const float* bn_beta  = (const float*)d_in[16];
    const float* attn_w   = (const float*)d_in[17];
    const float* attn_u   = (const float*)d_in[18];
    const float* gc1_w    = (const float*)d_in[19];
    const float* gc1_b    = (const float*)d_in[20];
    const float* gc2_w    = (const float*)d_in[21];
    const float* gc2_b    = (const float*)d_in[22];
    const float* fin1_w   = (const float*)d_in[23];
    const float* fin1_b   = (const float*)d_in[24];
    const float* fin2_w   = (const float*)d_in[25];
    const float* fin2_b   = (const float*)d_in[26];
    float* out = (float*)d_out;

    float* buf; int* deg;
    cudaGetSymbolAddress((void**)&buf, g_buf);
    cudaGetSymbolAddress((void**)&deg, g_deg);

    float* wA = buf + OFF_WA;
    float* wB = buf + OFF_WB;
    // regions indexed by ORIGINAL branch (0=K3,1=K5,2=K9)
    const size_t wA_off[3] = {0, 3 * (size_t)DD * FP, 8 * (size_t)DD * FP};
    const size_t wB_off[6] = {0, 3 * (size_t)FP * FP,
                              6 * (size_t)FP * FP, 11 * (size_t)FP * FP,
                              16 * (size_t)FP * FP, 25 * (size_t)FP * FP};

    PrepPtrs P;
    P.cw0 = convw3; P.cw1 = convw5; P.cw2 = convw9;
    P.rw0 = resw3;  P.rw1 = resw5;  P.rw2 = resw9;
    P.aw = attn_w;  P.au = attn_u;
    P.gc1 = gc1_w;  P.gc2 = gc2_w;  P.f1 = fin1_w;
    P.wA0 = wA + wA_off[0]; P.wA1 = wA + wA_off[1]; P.wA2 = wA + wA_off[2];
    P.wB0 = wB + wB_off[0]; P.wB1 = wB + wB_off[1]; P.wB2 = wB + wB_off[2];
    P.wB3 = wB + wB_off[3]; P.wB4 = wB + wB_off[4]; P.wB5 = wB + wB_off[5];
    P.awp = buf + OFF_AWP; P.aup = buf + OFF_AUP;
    P.gwt = buf + OFF_GWT; P.f1T = buf + OFF_F1T;

    // zslot s: 0->K9 (orig 2), 1->K5 (orig 1), 2->K3 (orig 0)
    const int obr[3] = {2, 1, 0};
    const float* cbs[3]  = {convb9, convb5, convb3};
    float* t0s[3]; float* t1s[3];
    for (int s = 0; s < 3; s++) {
        t0s[s] = buf + OFF_T0 + (size_t)s * T0SZ;
        t1s[s] = buf + OFF_T1 + (size_t)s * T0SZ;
    }

    cudaFuncSetAttribute(k_conv_multi<DD>, cudaFuncAttributeMaxDynamicSharedMemorySize,
                         conv_multi_smem());
    cudaFuncSetAttribute(k_conv_multi<FP>, cudaFuncAttributeMaxDynamicSharedMemorySize,
                         conv_multi_smem());

    // launch 1: embed; 2: preps; 3: deg init; 4: merged conv phase1 (profiled)
    k_embed<<<(int)(((size_t)BB * LL * DD + 255) / 256), 256>>>(x, word_emb, buf + OFF_H);
    k_prep_all<<<dim3(1152, 18), 256>>>(P);
    k_deginit<<<(BB * NN + 255) / 256, 256>>>(deg);

    dim3 cgrid(LL / 128, BB, 3);

    ConvMulti A1;
    for (int s = 0; s < 3; s++) {
        int ob = obr[s];
        A1.in[s] = buf + OFF_H;
        A1.wT[s] = wA + wA_off[ob];
        A1.cb[s] = cbs[s];
        A1.gma[s] = bn_gamma + (size_t)ob * 3 * FF;
        A1.bta[s] = bn_beta + (size_t)ob * 3 * FF;
        A1.resid[s] = nullptr;
        A1.out[s] = t0s[s];
    }
    A1.mode = 0;
    k_conv_multi<DD><<<cgrid, 256, conv_multi_smem()>>>(A1);

    ConvMulti A2;
    for (int s = 0; s < 3; s++) {
        int ob = obr[s];
        A2.in[s] = t0s[s];
        A2.wT[s] = wB + wB_off[ob * 2 + 0];
        A2.cb[s] = nullptr;
        A2.gma[s] = bn_gamma + (size_t)ob * 3 * FF + FF;
        A2.bta[s] = bn_beta + (size_t)ob * 3 * FF + FF;
        A2.resid[s] = t0s[s];
        A2.out[s] = t1s[s];
    }
    A2.mode = 1;
    k_conv_multi<FP><<<cgrid, 256, conv_multi_smem()>>>(A2);

    ConvMulti A3;
    for (int s = 0; s < 3; s++) {
        int ob = obr[s];
        A3.in[s] = t1s[s];
        A3.wT[s] = wB + wB_off[ob * 2 + 1];
        A3.cb[s] = nullptr;
        A3.gma[s] = bn_gamma + (size_t)ob * 3 * FF + 2 * FF;
        A3.bta[s] = bn_beta + (size_t)ob * 3 * FF + 2 * FF;
        A3.resid[s] = t1s[s];
        A3.out[s] = t0s[s];
    }
    A3.mode = 1;
    k_conv_multi<FP><<<cgrid, 256, conv_multi_smem()>>>(A3);

    // merged attention GEMMs
    Ptr3 btZ, btL;
    for (int s = 0; s < 3; s++) {
        btZ.p[s] = buf + OFF_AWP + (size_t)obr[s] * FP * AA;
        btL.p[s] = buf + OFF_AUP + (size_t)obr[s] * AA * 64;
    }
    // Z[s][b][l][a] = tanh(t0 . aw^T)
    k_mma_nt3<FP, 2, true, false><<<dim3(LL / 128, AA / 128, 48), 256>>>(
        buf + OFF_T0, btZ, buf + OFF_Z, AA,
        T0SZ, (size_t)LL * FP, ZSZ, (size_t)LL * AA, AA, 0);
    // logits[s][b][c][l] = Z . au^T (transposed store)
    k_mma_nt3<AA, 1, false, true><<<dim3(LL / 128, 1, 48), 128>>>(
        buf + OFF_Z, btL, buf + OFF_LOG, 64,
        ZSZ, (size_t)LL * AA, LOGSZ, (size_t)CC * LL, 0, CC);

    k_soft<<<dim3(CC, BB, 3), 256>>>(buf + OFF_LOG, buf + OFF_RMAX, buf + OFF_RSINV);
    k_v<<<dim3(2, 16, 48), 128>>>(buf + OFF_T0, buf + OFF_LOG,
                                  buf + OFF_RMAX, buf + OFF_RSINV, buf + OFF_VPART);
    k_vred<<<(int)((3 * VSZ + 255) / 256), 256>>>(buf + OFF_VPART, buf + OFF_V);

    // GCN
    float* xn   = buf + OFF_XN;
    float* xw   = buf + OFF_XW;
    float* g1   = buf + OFF_G1;
    float* gout = buf + OFF_GOUT;
    float* dinv = buf + OFF_DINV;
    float* gwt1 = buf + OFF_GWT;
    float* gwt2 = buf + OFF_GWT + (size_t)DD * DD;
    k_nodes<<<(int)(((size_t)BB * NN * DD + 255) / 256), 256>>>(nodes, ent_emb, xn);
    k_degadd<<<(BB * EE + 255) / 256, 256>>>(edges, deg);
    k_dinv<<<(BB * NN + 255) / 256, 256>>>(deg, dinv);

    k_mma_nt<DD, 2, false, false><<<dim3(NN / 128, DD / 128, BB), 256>>>(
        xn, gwt1, xw, DD, (size_t)NN * DD, (size_t)NN * DD, DD, 0);
    k_self<<<(int)(((size_t)BB * NN * DD + 255) / 256), 256>>>(xw, dinv, g1, NN);
    k_edge<<<dim3(EE / 8, BB), 256>>>(edges, dinv, xw, g1, NN);
    k_post<<<(int)(((size_t)BB * NN * DD + 255) / 256), 256>>>(g1, gc1_b, NN, 1);

    k_mma_nt<DD, 2, false, false><<<dim3(NN / 128, DD / 128, BB), 256>>>(
        g1, gwt2, xw, DD, (size_t)NN * DD, (size_t)NN * DD, DD, 0);
    k_self<<<(int)(((size_t)BB * CC * DD + 255) / 256), 256>>>(xw, dinv, gout, CC);
    k_edge<<<dim3(EE / 8, BB), 256>>>(edges, dinv, xw, gout, CC);
    k_post<<<(int)(((size_t)BB * CC * DD + 255) / 256), 256>>>(gout, gc2_b, CC, 0);

    // final MLP
    k_final<<<dim3(CC, BB), FFNH>>>(gout, buf + OFF_V, buf + OFF_F1T,
                                    fin1_b, fin2_w, fin2_b, out);
}

// round 17
// speedup vs baseline: 1.5141x; 1.0451x over previous
#include <cuda_runtime.h>
#include <math.h>
#include <stdint.h>

#define BB   16
#define LL   4096
#define DD   256
#define CC   50
#define NN   512
#define EE   8192
#define FF   100
#define FP   128
#define AA   256
#define FFNH 128
#define FEAT 556   /* 256 + 3*100 */

static constexpr size_t T0SZ  = (size_t)BB*LL*FP;
static constexpr size_t ZSZ   = (size_t)BB*LL*AA;
static constexpr size_t LOGSZ = (size_t)BB*CC*LL;
static constexpr size_t VPSZ  = (size_t)16*BB*CC*FF;
static constexpr size_t VSZ   = (size_t)BB*CC*FF;

// ---------------- one big static scratch buffer (no allocations) ------------
static constexpr size_t OFF_H     = 0;
static constexpr size_t OFF_T0    = OFF_H     + (size_t)BB*LL*DD;
static constexpr size_t OFF_T1    = OFF_T0    + 3*T0SZ;
static constexpr size_t OFF_Z     = OFF_T1    + 3*T0SZ;
static constexpr size_t OFF_LOG   = OFF_Z     + 3*ZSZ;
static constexpr size_t OFF_RMAX  = OFF_LOG   + 3*LOGSZ;
static constexpr size_t OFF_RSINV = OFF_RMAX  + (size_t)3*BB*CC;
static constexpr size_t OFF_VPART = OFF_RSINV + (size_t)3*BB*CC;
static constexpr size_t OFF_V     = OFF_VPART + 3*VPSZ;
static constexpr size_t OFF_WA    = OFF_V     + 3*VSZ;
static constexpr size_t OFF_WB    = OFF_WA    + (size_t)3*9*DD*FP;
static constexpr size_t OFF_AWP   = OFF_WB    + (size_t)6*9*FP*FP;
static constexpr size_t OFF_AUP   = OFF_AWP   + (size_t)3*FP*AA;
static constexpr size_t OFF_GWT   = OFF_AUP   + (size_t)3*AA*64;
static constexpr size_t OFF_XN    = OFF_GWT   + (size_t)2*DD*DD;
static constexpr size_t OFF_XW    = OFF_XN    + (size_t)BB*NN*DD;
static constexpr size_t OFF_G1    = OFF_XW    + (size_t)BB*NN*DD;
static constexpr size_t OFF_GOUT  = OFF_G1    + (size_t)BB*NN*DD;
static constexpr size_t OFF_F1T   = OFF_GOUT  + (size_t)BB*CC*DD;
static constexpr size_t OFF_DINV  = OFF_F1T   + (size_t)FEAT*FFNH;
static constexpr size_t BUF_TOTAL = OFF_DINV  + (size_t)BB*NN;

__device__ float g_buf[BUF_TOTAL];
__device__ int   g_deg[BB*NN];

// ---------------- helpers ----------------------------------------------------
__device__ __forceinline__ float to_tf32(float x) {
    float r;
    asm("cvt.rna.tf32.f32 %0, %1;" : "=f"(r) : "f"(x));
    return r;
}

__device__ __forceinline__ void mma8(float d[4], const uint32_t a[4],
                                     uint32_t b0, uint32_t b1) {
    asm volatile(
        "mma.sync.aligned.m16n8k8.row.col.f32.tf32.tf32.f32 "
        "{%0,%1,%2,%3}, {%4,%5,%6,%7}, {%8,%9}, {%0,%1,%2,%3};\n"
        : "+f"(d[0]), "+f"(d[1]), "+f"(d[2]), "+f"(d[3])
        : "r"(a[0]), "r"(a[1]), "r"(a[2]), "r"(a[3]), "r"(b0), "r"(b1));
}

__device__ __forceinline__ void cp16(float* dst_smem, const float* src, bool pred) {
    uint32_t d = (uint32_t)__cvta_generic_to_shared(dst_smem);
    int sz = pred ? 16 : 0;
    asm volatile("cp.async.cg.shared.global [%0], [%1], 16, %2;\n"
                 :: "r"(d), "l"(src), "r"(sz));
}
__device__ __forceinline__ void cp_commit() {
    asm volatile("cp.async.commit_group;\n");
}
__device__ __forceinline__ void cp_wait0() {
    asm volatile("cp.async.wait_group 0;\n");
}
__device__ __forceinline__ void cp_wait1() {
    asm volatile("cp.async.wait_group 1;\n");
}

// ---------------- embedding gather  h[b][l][d] (tf32-rounded) ----------------
__global__ void k_embed(const int* __restrict__ x, const float* __restrict__ emb,
                        float* __restrict__ h) {
    size_t idx = (size_t)blockIdx.x * 256 + threadIdx.x;
    if (idx >= (size_t)BB*LL*DD) return;
    int d = (int)(idx & (DD - 1));
    size_t row = idx >> 8;
    h[idx] = to_tf32(emb[(size_t)x[row] * DD + d]);
}

// ---------------- merged prep kernel (18 segments) ---------------------------
struct PrepPtrs {
    const float *cw0, *cw1, *cw2;     // convw3/5/9 [F][DD][K]
    const float *rw0, *rw1, *rw2;     // resw3/5/9  [2][F][FF][K]
    const float *aw, *au, *gc1, *gc2, *f1;
    float *wA0, *wA1, *wA2;
    float *wB0, *wB1, *wB2, *wB3, *wB4, *wB5;
    float *awp, *aup, *gwt, *f1T;
};

__global__ void k_prep_all(PrepPtrs P) {
    int seg = blockIdx.y;
    int idx0 = blockIdx.x * 256 + threadIdx.x;
    int stride = gridDim.x * 256;
    if (seg < 3) {                       // wA: [K][DD][FP], CIN=DD
        int K = (seg == 0) ? 3 : (seg == 1) ? 5 : 9;
        const float* src = (seg == 0) ? P.cw0 : (seg == 1) ? P.cw1 : P.cw2;
        float* dst = (seg == 0) ? P.wA0 : (seg == 1) ? P.wA1 : P.wA2;
        int tot = K * DD * FP;
        for (int idx = idx0; idx < tot; idx += stride) {
            int f = idx & 127;
            int rem = idx >> 7;
            int d = rem % DD;
            int k = rem / DD;
            dst[idx] = (f < FF) ? to_tf32(src[(f * DD + d) * K + k]) : 0.f;
        }
    } else if (seg < 9) {                // wB: [K][FP][FP], CIN=FF
        int inst = seg - 3, br = inst >> 1, which = inst & 1;
        int K = (br == 0) ? 3 : (br == 1) ? 5 : 9;
        const float* base = (br == 0) ? P.rw0 : (br == 1) ? P.rw1 : P.rw2;
        const float* src = base + (size_t)which * FF * FF * K;
        float* dst = (inst == 0) ? P.wB0 : (inst == 1) ? P.wB1 : (inst == 2) ? P.wB2 :
                     (inst == 3) ? P.wB3 : (inst == 4) ? P.wB4 : P.wB5;
        int tot = K * FP * FP;
        for (int idx = idx0; idx < tot; idx += stride) {
            int f = idx & 127;
            int rem = idx >> 7;
            int d = rem % FP;
            int k = rem / FP;
            dst[idx] = (f < FF && d < FF) ? to_tf32(src[(f * FF + d) * K + k]) : 0.f;
        }
    } else if (seg < 12) {               // awp: Bt[k(FP)][a(AA)]
        int br = seg - 9;
        const float* src = P.aw + (size_t)br * AA * FF;
        float* dst = P.awp + (size_t)br * FP * AA;
        int tot = FP * AA;
        for (int idx = idx0; idx < tot; idx += stride) {
            int k = idx >> 8, n = idx & (AA - 1);
            dst[idx] = (k < FF) ? to_tf32(src[n * FF + k]) : 0.f;
        }
    } else if (seg < 15) {               // aup: Bt[k(AA)][c(64)]
        int br = seg - 12;
        const float* src = P.au + (size_t)br * CC * AA;
        float* dst = P.aup + (size_t)br * AA * 64;
        int tot = AA * 64;
        for (int idx = idx0; idx < tot; idx += stride) {
            int k = idx >> 6, n = idx & 63;
            dst[idx] = (n < CC) ? to_tf32(src[n * AA + k]) : 0.f;
        }
    } else if (seg < 17) {               // GCN weight transposes
        const float* src = (seg == 15) ? P.gc1 : P.gc2;
        float* dst = P.gwt + (size_t)(seg - 15) * DD * DD;
        int tot = DD * DD;
        for (int idx = idx0; idx < tot; idx += stride) {
            int k = idx >> 8, n = idx & (DD - 1);
            dst[idx] = to_tf32(src[n * DD + k]);
        }
    } else {                             // f1T
        int tot = FEAT * FFNH;
        for (int idx = idx0; idx < tot; idx += stride) {
            int h = idx & (FFNH - 1), k = idx >> 7;
            P.f1T[idx] = P.f1[h * FEAT + k];
        }
    }
}

// ---------------- conv body: double-buffered input AND weights ---------------
template<int K, int CINP>
__device__ __forceinline__ void conv_body(
    const float* __restrict__ in, const float* __restrict__ wT,
    const float* __restrict__ cb, const float* __restrict__ gamma,
    const float* __restrict__ beta, const float* __restrict__ resid,
    float* __restrict__ out, int mode, float* smem) {
    constexpr int LT = 128;
    constexpr int PAD = K / 2;
    constexpr int ROWS = LT + K - 1;
    constexpr int ISTR = 36;
    constexpr int ITILE = ROWS * ISTR;
    constexpr int WSTR = 136;
    constexpr int WTILE = 32 * WSTR;
    constexpr int NC = CINP / 32;
    float* s_in = smem;                 // 2 * ITILE
    float* s_w  = smem + 2 * ITILE;     // 2 * WTILE

    int b = blockIdx.y, l0 = blockIdx.x * LT, tid = threadIdx.x;
    int wid = tid >> 5, lane = tid & 31;
    int wl = wid >> 1, wf = wid & 1;
    int grp = lane >> 2, thr = lane & 3;

    float acc[2][8][4];
#pragma unroll
    for (int mi = 0; mi < 2; mi++)
#pragma unroll
        for (int ni = 0; ni < 8; ni++)
#pragma unroll
            for (int ci = 0; ci < 4; ci++) acc[mi][ni][ci] = 0.f;

    const float* inb = in + (size_t)b * LL * CINP;

    auto fill_input = [&](int c, int bufi) {
        float* dst = s_in + bufi * ITILE;
        for (int t = tid; t < ROWS * 8; t += 256) {
            int row = t >> 3, seg = t & 7;
            int gl = l0 - PAD + row;
            cp16(&dst[row * ISTR + seg * 4],
                 inb + (size_t)gl * CINP + c * 32 + seg * 4,
                 (gl >= 0 && gl < LL));
        }
    };
    auto fill_w = [&](int kk, int cc, int bufw) {
        const float* wk = wT + ((size_t)kk * CINP + cc * 32) * FP;
        float* dst = s_w + bufw * WTILE;
        for (int t = tid; t < 32 * 32; t += 256) {
            int dd = t >> 5, seg = t & 31;
            cp16(&dst[dd * WSTR + seg * 4], wk + dd * FP + seg * 4, true);
        }
    };

    fill_input(0, 0);
    fill_w(0, 0, 0);
    cp_commit();
    cp_wait0();
    __syncthreads();

    for (int c = 0; c < NC; c++) {
        int cur = c & 1;
        const float* sin = s_in + cur * ITILE;
#pragma unroll
        for (int k = 0; k < K; k++) {
            int g = c * K + k;
            bool haveW = (g + 1 < NC * K);
            if (haveW) {
                int nk = (k + 1 < K) ? k + 1 : 0;
                int ncd = (k + 1 < K) ? c : c + 1;
                fill_w(nk, ncd, (g + 1) & 1);
                cp_commit();
            }
            bool haveI = (k == 0 && c + 1 < NC);
            if (haveI) {
                fill_input(c + 1, 1 - cur);
                cp_commit();
            }
            const float* curw = s_w + (g & 1) * WTILE;
#pragma unroll
            for (int ds = 0; ds < 32; ds += 8) {
                uint32_t a[2][4];
#pragma unroll
                for (int mi = 0; mi < 2; mi++) {
                    int r0 = wl * 32 + mi * 16 + grp + k;
                    a[mi][0] = __float_as_uint(sin[r0 * ISTR + ds + thr]);
                    a[mi][1] = __float_as_uint(sin[(r0 + 8) * ISTR + ds + thr]);
                    a[mi][2] = __float_as_uint(sin[r0 * ISTR + ds + thr + 4]);
                    a[mi][3] = __float_as_uint(sin[(r0 + 8) * ISTR + ds + thr + 4]);
                }
#pragma unroll
                for (int ni = 0; ni < 8; ni++) {
                    int f = wf * 64 + ni * 8 + grp;
                    uint32_t b0 = __float_as_uint(curw[(ds + thr) * WSTR + f]);
                    uint32_t b1 = __float_as_uint(curw[(ds + thr + 4) * WSTR + f]);
                    mma8(acc[0][ni], a[0], b0, b1);
                    mma8(acc[1][ni], a[1], b0, b1);
                }
            }
            if (haveI && haveW) cp_wait1();
            else cp_wait0();
            __syncthreads();
        }
    }

    const float BNI = rsqrtf(1.f + 1e-5f);
#pragma unroll
    for (int mi = 0; mi < 2; mi++) {
#pragma unroll
        for (int ci = 0; ci < 4; ci++) {
            int l = l0 + wl * 32 + mi * 16 + grp + ((ci >= 2) ? 8 : 0);
            size_t base = ((size_t)b * LL + l) * FP;
#pragma unroll
            for (int ni = 0; ni < 8; ni++) {
                int f = wf * 64 + ni * 8 + 2 * thr + (ci & 1);
                float v = acc[mi][ni][ci];
                float o;
                if (f < FF) {
                    float sc = gamma[f] * BNI, bt = beta[f];
                    if (mode == 0) o = tanhf(v + cb[f]) * sc + bt;
                    else           o = tanhf(v * sc + bt + resid[base + f]);
                    o = to_tf32(o);
                } else {
                    o = 0.f;
                }
                out[base + f] = o;
            }
        }
    }
}

// Merged 3-branch conv: z=0 -> K9, z=1 -> K5, z=2 -> K3 (heavy first)
struct ConvMulti {
    const float* in[3];
    const float* wT[3];
    const float* cb[3];
    const float* gma[3];
    const float* bta[3];
    const float* resid[3];
    float* out[3];
    int mode;
};

template<int CINP>
__global__ void __launch_bounds__(256, 2) k_conv_multi(ConvMulti A) {
    extern __shared__ float smem[];
    int s = blockIdx.z;
    if (s == 0)
        conv_body<9, CINP>(A.in[0], A.wT[0], A.cb[0], A.gma[0], A.bta[0],
                           A.resid[0], A.out[0], A.mode, smem);
    else if (s == 1)
        conv_body<5, CINP>(A.in[1], A.wT[1], A.cb[1], A.gma[1], A.bta[1],
                           A.resid[1], A.out[1], A.mode, smem);
    else
        conv_body<3, CINP>(A.in[2], A.wT[2], A.cb[2], A.gma[2], A.bta[2],
                           A.resid[2], A.out[2], A.mode, smem);
}

static constexpr int conv_multi_smem() {
    return (2 * (128 + 9 - 1) * 36 + 2 * 32 * 136) * 4;   // max over K
}

// ---------------- generic tf32 NT GEMM bodies -------------------------------
template<int CINP, int WF, bool TANH, bool TRANSOUT>
__device__ __forceinline__ void mma_nt_body(
    const float* __restrict__ A, const float* __restrict__ Bt,
    float* __restrict__ out, int nstride, int ostr, int cclamp) {
    constexpr int NT = WF * 128;
    constexpr int WIDTH = WF * 64;
    constexpr int WSTR = WIDTH + 8;
    __shared__ float s_a[128 * 36];
    __shared__ float s_w[32 * WSTR];
    int m0 = blockIdx.x * 128;
    int n0 = blockIdx.y * WIDTH;
    int tid = threadIdx.x;
    int wid = tid >> 5, lane = tid & 31;
    int wl = wid / WF, wf = wid % WF;
    int grp = lane >> 2, thr = lane & 3;

    float acc[2][8][4];
#pragma unroll
    for (int mi = 0; mi < 2; mi++)
#pragma unroll
        for (int ni = 0; ni < 8; ni++)
#pragma unroll
            for (int ci = 0; ci < 4; ci++) acc[mi][ni][ci] = 0.f;

    for (int k0 = 0; k0 < CINP; k0 += 32) {
        __syncthreads();
        for (int t = tid; t < 128 * 8; t += NT) {
            int row = t >> 3, seg = t & 7;
            cp16(&s_a[row * 36 + seg * 4],
                 A + (size_t)(m0 + row) * CINP + k0 + seg * 4, true);
        }
        for (int t = tid; t < 32 * (WIDTH / 4); t += NT) {
            int dd = t / (WIDTH / 4), seg = t % (WIDTH / 4);
            cp16(&s_w[dd * WSTR + seg * 4],
                 Bt + (size_t)(k0 + dd) * nstride + n0 + seg * 4, true);
        }
        cp_commit();
        cp_wait0();
        __syncthreads();
#pragma unroll
        for (int ds = 0; ds < 32; ds += 8) {
            uint32_t a[2][4];
#pragma unroll
            for (int mi = 0; mi < 2; mi++) {
                int r0 = wl * 32 + mi * 16 + grp;
                a[mi][0] = __float_as_uint(s_a[r0 * 36 + ds + thr]);
                a[mi][1] = __float_as_uint(s_a[(r0 + 8) * 36 + ds + thr]);
                a[mi][2] = __float_as_uint(s_a[r0 * 36 + ds + thr + 4]);
                a[mi][3] = __float_as_uint(s_a[(r0 + 8) * 36 + ds + thr + 4]);
            }
#pragma unroll
            for (int ni = 0; ni < 8; ni++) {
                int f = wf * 64 + ni * 8 + grp;
                uint32_t b0 = __float_as_uint(s_w[(ds + thr) * WSTR + f]);
                uint32_t b1 = __float_as_uint(s_w[(ds + thr + 4) * WSTR + f]);
                mma8(acc[0][ni], a[0], b0, b1);
                mma8(acc[1][ni], a[1], b0, b1);
            }
        }
    }

#pragma unroll
    for (int mi = 0; mi < 2; mi++) {
#pragma unroll
        for (int ci = 0; ci < 4; ci++) {
            int mrow = wl * 32 + mi * 16 + grp + ((ci >= 2) ? 8 : 0);
#pragma unroll
            for (int ni = 0; ni < 8; ni++) {
                int n = wf * 64 + ni * 8 + 2 * thr + (ci & 1);
                float v = acc[mi][ni][ci];
                if (TANH) v = to_tf32(tanhf(v));
                if (TRANSOUT) {
                    int c = n0 + n;
                    if (c < cclamp) out[(size_t)c * LL + m0 + mrow] = v;
                } else {
                    out[(size_t)(m0 + mrow) * ostr + n0 + n] = v;
                }
            }
        }
    }
}

template<int CINP, int WF, bool TANH, bool TRANSOUT>
__global__ void k_mma_nt(const float* __restrict__ A, const float* __restrict__ Bt,
                         float* __restrict__ out, int nstride,
                         size_t a_bstr, size_t o_bstr, int ostr, int cclamp) {
    int b = blockIdx.z;
    mma_nt_body<CINP, WF, TANH, TRANSOUT>(
        A + (size_t)b * a_bstr, Bt, out + (size_t)b * o_bstr,
        nstride, ostr, cclamp);
}

// 3-branch merged variant: z = s*BB + b; Bt selected per branch
struct Ptr3 { const float* p[3]; };

template<int CINP, int WF, bool TANH, bool TRANSOUT>
__global__ void k_mma_nt3(const float* __restrict__ A, Ptr3 bt,
                          float* __restrict__ out, int nstride,
                          size_t a_brstr, size_t a_bstr,
                          size_t o_brstr, size_t o_bstr, int ostr, int cclamp) {
    int z = blockIdx.z;
    int s = z >> 4, b = z & 15;
    mma_nt_body<CINP, WF, TANH, TRANSOUT>(
        A + (size_t)s * a_brstr + (size_t)b * a_bstr, bt.p[s],
        out + (size_t)s * o_brstr + (size_t)b * o_bstr,
        nstride, ostr, cclamp);
}

// ---------------- softmax stats (merged over branches via z) ----------------
__global__ void k_soft(const float* __restrict__ logits, float* __restrict__ rmax,
                       float* __restrict__ rsinv) {
    __shared__ float sred[256];
    int c = blockIdx.x, b = blockIdx.y, s = blockIdx.z, tid = threadIdx.x;
    const float* row = logits + (size_t)s * LOGSZ + ((size_t)b * CC + c) * LL;
    int sidx = s * BB * CC + b * CC + c;
    float m = -1e30f;
    for (int l = tid; l < LL; l += 256) m = fmaxf(m, row[l]);
    sred[tid] = m; __syncthreads();
    for (int st = 128; st > 0; st >>= 1) {
        if (tid < st) sred[tid] = fmaxf(sred[tid], sred[tid + st]);
        __syncthreads();
    }
    m = sred[0]; __syncthreads();
    float sum = 0.f;
    for (int l = tid; l < LL; l += 256) sum += expf(row[l] - m);
    sred[tid] = sum; __syncthreads();
    for (int st = 128; st > 0; st >>= 1) {
        if (tid < st) sred[tid] += sred[tid + st];
        __syncthreads();
    }
    if (tid == 0) { rmax[sidx] = m; rsinv[sidx] = 1.f / sred[0]; }
}

// ---------------- V partials (merged, float4 weights): z = s*BB + b ---------
__global__ void k_v(const float* __restrict__ tbase, const float* __restrict__ lgbase,
                    const float* __restrict__ rmax, const float* __restrict__ rsinv,
                    float* __restrict__ vpbase) {
    __shared__ float4 s_w4[25][64];
    float* s_wf = reinterpret_cast<float*>(s_w4);
    int cgrp = blockIdx.x, chunk = blockIdx.y;
    int z = blockIdx.z, s = z >> 4, b = z & 15;
    const float* t  = tbase + (size_t)s * T0SZ;
    const float* lg = lgbase + (size_t)s * LOGSZ;
    float* vpart = vpbase + (size_t)s * VPSZ;
    int tid = threadIdx.x;                 // 128 threads
    int l0 = chunk * 256;
    for (int idx = tid; idx < 25 * 256; idx += 128) {
        int cl = idx >> 8, ll = idx & 255;
        int c = cgrp * 25 + cl;
        int sidx = s * BB * CC + b * CC + c;
        float m = rmax[sidx], si = rsinv[sidx];
        s_wf[cl * 256 + ll] = expf(lg[((size_t)b * CC + c) * LL + l0 + ll] - m) * si;
    }
    __syncthreads();
    float acc[25];
#pragma unroll
    for (int c = 0; c < 25; c++) acc[c] = 0.f;
    int f = tid;
    bool valid = (f < FF);
    for (int ll4 = 0; ll4 < 64; ll4++) {
        float tv0 = valid ? t[((size_t)b * LL + l0 + ll4 * 4 + 0) * FP + f] : 0.f;
        float tv1 = valid ? t[((size_t)b * LL + l0 + ll4 * 4 + 1) * FP + f] : 0.f;
        float tv2 = valid ? t[((size_t)b * LL + l0 + ll4 * 4 + 2) * FP + f] : 0.f;
        float tv3 = valid ? t[((size_t)b * LL + l0 + ll4 * 4 + 3) * FP + f] : 0.f;
#pragma unroll
        for (int c = 0; c < 25; c++) {
            float4 wv = s_w4[c][ll4];
            acc[c] += wv.x * tv0 + wv.y * tv1 + wv.z * tv2 + wv.w * tv3;
        }
    }
    if (valid) {
#pragma unroll
        for (int c = 0; c < 25; c++) {
            int cg = cgrp * 25 + c;
            vpart[(((size_t)chunk * BB + b) * CC + cg) * FF + f] = acc[c];
        }
    }
}

// zslot s -> original branch (2-s) for the concat-ordered V region
__global__ void k_vred(const float* __restrict__ vpbase, float* __restrict__ V) {
    size_t idx = (size_t)blockIdx.x * 256 + threadIdx.x;
    if (idx >= 3 * VSZ) return;
    int s = (int)(idx / VSZ);
    size_t rem = idx % VSZ;
    float sum = 0.f;
#pragma unroll
    for (int ch = 0; ch < 16; ch++)
        sum += vpbase[(size_t)s * VPSZ + (size_t)ch * VSZ + rem];
    V[(size_t)(2 - s) * VSZ + rem] = sum;
}

// ---------------- GCN ------------------------------------------------------
__global__ void k_nodes(const int* __restrict__ nodes, const float* __restrict__ emb,
                        float* __restrict__ xn) {
    size_t idx = (size_t)blockIdx.x * 256 + threadIdx.x;
    if (idx >= (size_t)BB * NN * DD) return;
    int d = (int)(idx & (DD - 1));
    size_t row = idx >> 8;
    xn[idx] = to_tf32(emb[(size_t)nodes[row] * DD + d]);
}

__global__ void k_deginit(int* __restrict__ deg) {
    int idx = blockIdx.x * 256 + threadIdx.x;
    if (idx < BB * NN) deg[idx] = 1;   // self loop
}

__global__ void k_degadd(const int* __restrict__ edges, int* __restrict__ deg) {
    int idx = blockIdx.x * 256 + threadIdx.x;
    if (idx >= BB * EE) return;
    int b = idx / EE, e = idx % EE;
    int dst = edges[(b * 2 + 1) * EE + e];
    atomicAdd(&deg[b * NN + dst], 1);
}

__global__ void k_dinv(const int* __restrict__ deg, float* __restrict__ dinv) {
    int idx = blockIdx.x * 256 + threadIdx.x;
    if (idx < BB * NN) dinv[idx] = rsqrtf((float)deg[idx]);
}

__global__ void k_self(const float* __restrict__ xw, const float* __restrict__ dinv,
                       float* __restrict__ out, int rows) {
    size_t idx = (size_t)blockIdx.x * 256 + threadIdx.x;
    if (idx >= (size_t)BB * rows * DD) return;
    int o = (int)(idx & (DD - 1));
    size_t row = idx >> 8;
    int b = (int)(row / rows);
    int n = (int)(row % rows);
    float di = dinv[b * NN + n];
    out[idx] = di * di * xw[((size_t)b * NN + n) * DD + o];
}

__global__ void k_edge(const int* __restrict__ edges, const float* __restrict__ dinv,
                       const float* __restrict__ xw, float* __restrict__ out,
                       int dstmax) {
    int b = blockIdx.y;
    int eloc = threadIdx.x >> 5, lane = threadIdx.x & 31;
    int e = blockIdx.x * 8 + eloc;
    int src = edges[(b * 2) * EE + e];
    int dst = edges[(b * 2 + 1) * EE + e];
    if (dst >= dstmax) return;
    float norm = dinv[b * NN + src] * dinv[b * NN + dst];
    const float* xr = xw + ((size_t)b * NN + src) * DD;
    float* orow = out + ((size_t)b * dstmax + dst) * DD;
#pragma unroll
    for (int j = 0; j < 8; j++) {
        int o = lane + j * 32;
        atomicAdd(&orow[o], norm * xr[o]);
    }
}

__global__ void k_post(float* __restrict__ buf, const float* __restrict__ bias,
                       int rows, int dorelu) {
    size_t idx = (size_t)blockIdx.x * 256 + threadIdx.x;
    if (idx >= (size_t)BB * rows * DD) return;
    int o = (int)(idx & (DD - 1));
    float v = buf[idx] + bias[o];
    if (dorelu) v = fmaxf(v, 0.f);
    buf[idx] = to_tf32(v);
}

// ---------------- final MLP --------------------------------------------------
__global__ void k_final(const float* __restrict__ gout, const float* __restrict__ V,
                        const float* __restrict__ f1T, const float* __restrict__ f1b,
                        const float* __restrict__ f2w, const float* __restrict__ f2b,
                        float* __restrict__ y) {
    __shared__ float s_feat[FEAT];
    __shared__ float s_red[FFNH];
    int c = blockIdx.x, b = blockIdx.y, h = threadIdx.x;   // 128 threads
    for (int idx = h; idx < FEAT; idx += FFNH) {
        float v;
        if (idx < DD) {
            v = gout[((size_t)b * CC + c) * DD + idx];
        } else {
            int br = (idx - DD) / FF;
            int f  = (idx - DD) % FF;
            v = V[(((size_t)br * BB + b) * CC + c) * FF + f];
        }
        s_feat[idx] = v;
    }
    __syncthreads();
    float acc = f1b[h];
    for (int k = 0; k < FEAT; k++) acc += f1T[k * FFNH + h] * s_feat[k];
    float hid = fmaxf(acc, 0.f);
    s_red[h] = f2w[c * FFNH + h] * hid;
    __syncthreads();
    for (int s = 64; s > 0; s >>= 1) {
        if (h < s) s_red[h] += s_red[h + s];
        __syncthreads();
    }
    if (h == 0) y[b * CC + c] = s_red[0] + f2b[c];
}

// ---------------- side-stream handles (created once; same work per call) ----
static cudaStream_t get_s2() {
    static cudaStream_t s = [] {
        cudaStream_t st;
        cudaStreamCreateWithFlags(&st, cudaStreamNonBlocking);
        return st;
    }();
    return s;
}
static cudaEvent_t get_ev(int which) {
    static cudaEvent_t e0 = [] {
        cudaEvent_t e; cudaEventCreateWithFlags(&e, cudaEventDisableTiming); return e;
    }();
    static cudaEvent_t e1 = [] {
        cudaEvent_t e; cudaEventCreateWithFlags(&e, cudaEventDisableTiming); return e;
    }();
    return which == 0 ? e0 : e1;
}

extern "C" void kernel_launch(void* const* d_in, const int* in_sizes, int n_in,
                              void* d_out, int out_size) {
    const int*   x        = (const int*)d_in[0];
    const int*   nodes    = (const int*)d_in[2];
    const int*   edges    = (const int*)d_in[3];
    const float* word_emb = (const float*)d_in[4];
    const float* ent_emb  = (const float*)d_in[5];
    const float* convw3   = (const float*)d_in[6];
    const float* convb3   = (const float*)d_in[7];
    const float* resw3    = (const float*)d_in[8];
    const float* convw5   = (const float*)d_in[9];
    const float* convb5   = (const float*)d_in[10];
    const float* resw5    = (const float*)d_in[11];
    const float* convw9   = (const float*)d_in[12];
    const float* convb9   = (const float*)d_in[13];
    const float* resw9    = (const float*)d_in[14];
    const float* bn_gamma = (const float*)d_in[15];
    const float* bn_beta  = (const float*)d_in[16];
    const float* attn_w   = (const float*)d_in[17];
    const float* attn_u   = (const float*)d_in[18];
    const float* gc1_w    = (const float*)d_in[19];
    const float* gc1_b    = (const float*)d_in[20];
    const float* gc2_w    = (const float*)d_in[21];
    const float* gc2_b    = (const float*)d_in[22];
    const float* fin1_w   = (const float*)d_in[23];
    const float* fin1_b   = (const float*)d_in[24];
    const float* fin2_w   = (const float*)d_in[25];
    const float* fin2_b   = (const float*)d_in[26];
    float* out = (float*)d_out;

    float* buf; int* deg;
    cudaGetSymbolAddress((void**)&buf, g_buf);
    cudaGetSymbolAddress((void**)&deg, g_deg);

    cudaStream_t s2 = get_s2();
    cudaEvent_t e1 = get_ev(0), e2 = get_ev(1);

    float* wA = buf + OFF_WA;
    float* wB = buf + OFF_WB;
    const size_t wA_off[3] = {0, 3 * (size_t)DD * FP, 8 * (size_t)DD * FP};
    const size_t wB_off[6] = {0, 3 * (size_t)FP * FP,
                              6 * (size_t)FP * FP, 11 * (size_t)FP * FP,
                              16 * (size_t)FP * FP, 25 * (size_t)FP * FP};

    PrepPtrs P;
    P.cw0 = convw3; P.cw1 = convw5; P.cw2 = convw9;
    P.rw0 = resw3;  P.rw1 = resw5;  P.rw2 = resw9;
    P.aw = attn_w;  P.au = attn_u;
    P.gc1 = gc1_w;  P.gc2 = gc2_w;  P.f1 = fin1_w;
    P.wA0 = wA + wA_off[0]; P.wA1 = wA + wA_off[1]; P.wA2 = wA + wA_off[2];
    P.wB0 = wB + wB_off[0]; P.wB1 = wB + wB_off[1]; P.wB2 = wB + wB_off[2];
    P.wB3 = wB + wB_off[3]; P.wB4 = wB + wB_off[4]; P.wB5 = wB + wB_off[5];
    P.awp = buf + OFF_AWP; P.aup = buf + OFF_AUP;
    P.gwt = buf + OFF_GWT; P.f1T = buf + OFF_F1T;

    const int obr[3] = {2, 1, 0};
    const float* cbs[3]  = {convb9, convb5, convb3};
    float* t0s[3]; float* t1s[3];
    for (int s = 0; s < 3; s++) {
        t0s[s] = buf + OFF_T0 + (size_t)s * T0SZ;
        t1s[s] = buf + OFF_T1 + (size_t)s * T0SZ;
    }

    cudaFuncSetAttribute(k_conv_multi<DD>, cudaFuncAttributeMaxDynamicSharedMemorySize,
                         conv_multi_smem());
    cudaFuncSetAttribute(k_conv_multi<FP>, cudaFuncAttributeMaxDynamicSharedMemorySize,
                         conv_multi_smem());

    // main launch 1: embed; 2: preps
    k_embed<<<(int)(((size_t)BB * LL * DD + 255) / 256), 256>>>(x, word_emb, buf + OFF_H);
    k_prep_all<<<dim3(1152, 18), 256>>>(P);

    // fork: GCN chain on s2 (needs gwt from preps)
    cudaEventRecord(e1, 0);
    cudaStreamWaitEvent(s2, e1, 0);

    float* xn   = buf + OFF_XN;
    float* xw   = buf + OFF_XW;
    float* g1   = buf + OFF_G1;
    float* gout = buf + OFF_GOUT;
    float* dinv = buf + OFF_DINV;
    float* gwt1 = buf + OFF_GWT;
    float* gwt2 = buf + OFF_GWT + (size_t)DD * DD;

    // launch 3 (s2): deginit — keeps merged conv phase1 at global index 4
    k_deginit<<<(BB * NN + 255) / 256, 256, 0, s2>>>(deg);

    // main launch 4: merged conv phase1 (profiled)
    dim3 cgrid(LL / 128, BB, 3);
    ConvMulti A1;
    for (int s = 0; s < 3; s++) {
        int ob = obr[s];
        A1.in[s] = buf + OFF_H;
        A1.wT[s] = wA + wA_off[ob];
        A1.cb[s] = cbs[s];
        A1.gma[s] = bn_gamma + (size_t)ob * 3 * FF;
        A1.bta[s] = bn_beta + (size_t)ob * 3 * FF;
        A1.resid[s] = nullptr;
        A1.out[s] = t0s[s];
    }
    A1.mode = 0;
    k_conv_multi<DD><<<cgrid, 256, conv_multi_smem()>>>(A1);

    ConvMulti A2;
    for (int s = 0; s < 3; s++) {
        int ob = obr[s];
        A2.in[s] = t0s[s];
        A2.wT[s] = wB + wB_off[ob * 2 + 0];
        A2.cb[s] = nullptr;
        A2.gma[s] = bn_gamma + (size_t)ob * 3 * FF + FF;
        A2.bta[s] = bn_beta + (size_t)ob * 3 * FF + FF;
        A2.resid[s] = t0s[s];
        A2.out[s] = t1s[s];
    }
    A2.mode = 1;
    k_conv_multi<FP><<<cgrid, 256, conv_multi_smem()>>>(A2);

    ConvMulti A3;
    for (int s = 0; s < 3; s++) {
        int ob = obr[s];
        A3.in[s] = t1s[s];
        A3.wT[s] = wB + wB_off[ob * 2 + 1];
        A3.cb[s] = nullptr;
        A3.gma[s] = bn_gamma + (size_t)ob * 3 * FF + 2 * FF;
        A3.bta[s] = bn_beta + (size_t)ob * 3 * FF + 2 * FF;
        A3.resid[s] = t1s[s];
        A3.out[s] = t0s[s];
    }
    A3.mode = 1;
    k_conv_multi<FP><<<cgrid, 256, conv_multi_smem()>>>(A3);

    // rest of GCN chain on s2 (runs concurrently with convs/attention)
    k_degadd<<<(BB * EE + 255) / 256, 256, 0, s2>>>(edges, deg);
    k_dinv<<<(BB * NN + 255) / 256, 256, 0, s2>>>(deg, dinv);
    k_nodes<<<(int)(((size_t)BB * NN * DD + 255) / 256), 256, 0, s2>>>(nodes, ent_emb, xn);
    k_mma_nt<DD, 2, false, false><<<dim3(NN / 128, DD / 128, BB), 256, 0, s2>>>(
        xn, gwt1, xw, DD, (size_t)NN * DD, (size_t)NN * DD, DD, 0);
    k_self<<<(int)(((size_t)BB * NN * DD + 255) / 256), 256, 0, s2>>>(xw, dinv, g1, NN);
    k_edge<<<dim3(EE / 8, BB), 256, 0, s2>>>(edges, dinv, xw, g1, NN);
    k_post<<<(int)(((size_t)BB * NN * DD + 255) / 256), 256, 0, s2>>>(g1, gc1_b, NN, 1);
    k_mma_nt<DD, 2, false, false><<<dim3(NN / 128, DD / 128, BB), 256, 0, s2>>>(
        g1, gwt2, xw, DD, (size_t)NN * DD, (size_t)NN * DD, DD, 0);
    k_self<<<(int)(((size_t)BB * CC * DD + 255) / 256), 256, 0, s2>>>(xw, dinv, gout, CC);
    k_edge<<<dim3(EE / 8, BB), 256, 0, s2>>>(edges, dinv, xw, gout, CC);
    k_post<<<(int)(((size_t)BB * CC * DD + 255) / 256), 256, 0, s2>>>(gout, gc2_b, CC, 0);
    cudaEventRecord(e2, s2);

    // main: merged attention
    Ptr3 btZ, btL;
    for (int s = 0; s < 3; s++) {
        btZ.p[s] = buf + OFF_AWP + (size_t)obr[s] * FP * AA;
        btL.p[s] = buf + OFF_AUP + (size_t)obr[s] * AA * 64;
    }
    k_mma_nt3<FP, 2, true, false><<<dim3(LL / 128, AA / 128, 48), 256>>>(
        buf + OFF_T0, btZ, buf + OFF_Z, AA,
        T0SZ, (size_t)LL * FP, ZSZ, (size_t)LL * AA, AA, 0);
    k_mma_nt3<AA, 1, false, true><<<dim3(LL / 128, 1, 48), 128>>>(
        buf + OFF_Z, btL, buf + OFF_LOG, 64,
        ZSZ, (size_t)LL * AA, LOGSZ, (size_t)CC * LL, 0, CC);

    k_soft<<<dim3(CC, BB, 3), 256>>>(buf + OFF_LOG, buf + OFF_RMAX, buf + OFF_RSINV);
    k_v<<<dim3(2, 16, 48), 128>>>(buf + OFF_T0, buf + OFF_LOG,
                                  buf + OFF_RMAX, buf + OFF_RSINV, buf + OFF_VPART);
    k_vred<<<(int)((3 * VSZ + 255) / 256), 256>>>(buf + OFF_VPART, buf + OFF_V);

    // join: final MLP needs both chains
    cudaStreamWaitEvent(0, e2, 0);
    k_final<<<dim3(CC, BB), FFNH>>>(gout, buf + OFF_V, buf + OFF_F1T,
                                    fin1_b, fin2_w, fin2_b, out);
}